// round 5
// baseline (speedup 1.0000x reference)
#include <cuda_runtime.h>
#include <cuda_bf16.h>
#include <stdint.h>

#define B_   4096
#define I_   256
#define H_   1024
#define N4H  4096
#define M_   4

// ---------------- scratch (device globals; no runtime allocation) ----------
__device__ float g_weff_ih[M_ * I_ * N4H];   // 16 MB
__device__ float g_weff_hh[M_ * H_ * N4H];   // 64 MB
__device__ float g_bq_ih[M_ * N4H];
__device__ float g_bn_ih[M_ * N4H];
__device__ float g_bq_hh[M_ * N4H];
__device__ float g_bn_hh[M_ * N4H];
__device__ unsigned char g_code_in[B_ * I_]; // 1 MB
__device__ unsigned char g_code_hx[B_ * H_]; // 4 MB
__device__ float g_gates[(size_t)B_ * N4H];  // 64 MB
__device__ float g_max[4];                   // wih, whh, bih, bhh

// ---------------- threefry2x32 (JAX exact) ---------------------------------
__host__ __device__ __forceinline__ uint32_t rotl32(uint32_t x, int r) {
    return (x << r) | (x >> (32 - r));
}

__host__ __device__ __forceinline__ void tf2x32(uint32_t k0, uint32_t k1,
                                                uint32_t x0, uint32_t x1,
                                                uint32_t* o0, uint32_t* o1) {
    uint32_t ks0 = k0, ks1 = k1, ks2 = k0 ^ k1 ^ 0x1BD11BDAu;
    x0 += ks0; x1 += ks1;
#define TF_RND(r) { x0 += x1; x1 = rotl32(x1, r); x1 ^= x0; }
    TF_RND(13) TF_RND(15) TF_RND(26) TF_RND(6)
    x0 += ks1; x1 += ks2 + 1u;
    TF_RND(17) TF_RND(29) TF_RND(16) TF_RND(24)
    x0 += ks2; x1 += ks0 + 2u;
    TF_RND(13) TF_RND(15) TF_RND(26) TF_RND(6)
    x0 += ks0; x1 += ks1 + 3u;
    TF_RND(17) TF_RND(29) TF_RND(16) TF_RND(24)
    x0 += ks1; x1 += ks2 + 4u;
    TF_RND(13) TF_RND(15) TF_RND(26) TF_RND(6)
    x0 += ks2; x1 += ks0 + 5u;
#undef TF_RND
    *o0 = x0; *o1 = x1;
}

// ---------------- XLA erf_inv (f32 Giles polynomial) ------------------------
__device__ __forceinline__ float erfinv_xla(float x) {
    float w = -log1pf(-__fmul_rn(x, x));
    float p;
    if (w < 5.0f) {
        w = w - 2.5f;
        p = 2.81022636e-08f;
        p = fmaf(p, w, 3.43273939e-07f);
        p = fmaf(p, w, -3.5233877e-06f);
        p = fmaf(p, w, -4.39150654e-06f);
        p = fmaf(p, w, 0.00021858087f);
        p = fmaf(p, w, -0.00125372503f);
        p = fmaf(p, w, -0.00417768164f);
        p = fmaf(p, w, 0.246640727f);
        p = fmaf(p, w, 1.50140941f);
    } else {
        w = sqrtf(w) - 3.0f;
        p = -0.000200214257f;
        p = fmaf(p, w, 0.000100950558f);
        p = fmaf(p, w, 0.00134934322f);
        p = fmaf(p, w, -0.00367342844f);
        p = fmaf(p, w, 0.00573950773f);
        p = fmaf(p, w, -0.0076224613f);
        p = fmaf(p, w, 0.00943887047f);
        p = fmaf(p, w, 1.00167406f);
        p = fmaf(p, w, 2.83297682f);
    }
    return __fmul_rn(p, x);
}

// normal sample from 32 random bits (jax uniform->erfinv path, exact)
__device__ __forceinline__ float normal_from_bits(uint32_t bits) {
    float f = __uint_as_float((bits >> 9) | 0x3f800000u) - 1.0f;  // [0,1)
    const float lo = -0.99999994f;  // nextafter(-1,0)
    float u = fmaxf(lo, __fadd_rn(__fmul_rn(f, 2.0f), lo));       // f*2 exact
    return __fmul_rn(1.41421356f, erfinv_xla(u));                 // 0x3FB504F3
}

// ---------------- small kernels --------------------------------------------
__global__ void k_init() {
    if (threadIdx.x < 4) g_max[threadIdx.x] = 0.0f;
}

__global__ void k_maxred(const float* __restrict__ x, int n, int slot) {
    float m = 0.0f;
    for (int i = blockIdx.x * blockDim.x + threadIdx.x; i < n;
         i += gridDim.x * blockDim.x)
        m = fmaxf(m, x[i]);
    for (int o = 16; o; o >>= 1)
        m = fmaxf(m, __shfl_xor_sync(0xffffffffu, m, o));
    if ((threadIdx.x & 31) == 0)
        atomicMax((int*)&g_max[slot], __float_as_int(m));  // m >= 0 always here
}

__device__ __forceinline__ float quant8(float x) {  // quant(x, 8, 1.0)
    float xs = fminf(fmaxf(x, -0.9921875f), 0.9921875f);
    return __fmul_rn(rintf(__fmul_rn(xs, 128.0f)), 0.0078125f);
}

// weff = quant(W,8,1) + (normal * max) * 0.1
__global__ void k_genw(const float* __restrict__ W, float* __restrict__ out,
                       int n, uint32_t k0, uint32_t k1, int maxslot) {
    int j = blockIdx.x * blockDim.x + threadIdx.x;
    if (j >= n) return;
    uint32_t o0, o1;
    tf2x32(k0, k1, 0u, (uint32_t)j, &o0, &o1);
    float nrm = normal_from_bits(o0 ^ o1);
    float wmax = g_max[maxslot];
    float noise = __fmul_rn(__fmul_rn(nrm, wmax), 0.1f);
    out[j] = __fadd_rn(quant8(W[j]), noise);
}

__global__ void k_genb(const float* __restrict__ bsrc, float* __restrict__ bq,
                       float* __restrict__ bn, int n,
                       uint32_t k0, uint32_t k1, int maxslot) {
    int j = blockIdx.x * blockDim.x + threadIdx.x;
    if (j >= n) return;
    uint32_t o0, o1;
    tf2x32(k0, k1, 0u, (uint32_t)j, &o0, &o1);
    float nrm = normal_from_bits(o0 ^ o1);
    float bmax = g_max[maxslot];
    bq[j] = quant8(bsrc[j]);
    bn[j] = __fmul_rn(__fmul_rn(nrm, bmax), 0.1f);
}

// code = int(rint(15 * (clip(x,+-ac)+off)/(2*ac))) & 15
__global__ void k_code(const float* __restrict__ x, unsigned char* __restrict__ code,
                       int n, const float* __restrict__ aclip,
                       const float* __restrict__ aoff) {
    int i = blockIdx.x * blockDim.x + threadIdx.x;
    if (i >= n) return;
    float ac = aclip[0], off = aoff[0];
    float denom = __fmul_rn(ac, 2.0f);
    float xc = fminf(fmaxf(x[i], -ac), ac);
    float v01 = __fdiv_rn(__fadd_rn(xc, off), denom);
    int v = (int)rintf(__fmul_rn(15.0f, v01));
    code[i] = (unsigned char)(v & 15);
}

// ---------------- packed f32x2 helpers --------------------------------------
__device__ __forceinline__ unsigned long long pk2(float x, float y) {
    unsigned long long r;
    asm("mov.b64 %0, {%1, %2};" : "=l"(r) : "f"(x), "f"(y));
    return r;
}
__device__ __forceinline__ void upk2(unsigned long long v, float& x, float& y) {
    asm("mov.b64 {%0, %1}, %2;" : "=f"(x), "=f"(y) : "l"(v));
}
__device__ __forceinline__ void fma2(unsigned long long& c, unsigned long long a,
                                     unsigned long long b) {
    asm("fma.rn.f32x2 %0, %1, %2, %0;" : "+l"(c) : "l"(a), "l"(b));
}

// ---------------- the plane-GEMM -------------------------------------------
// gates[b,n] (+)= (sum_m beta_m * (((sum_k bit_m(code[b,k])*weff[m,k,n]) + bq[m,n]) + bn[m,n] > 0.5)) * 2a - a
#define BM 128
#define BN 128
#define BKK 16

__global__ __launch_bounds__(256, 2)
void k_gemm(const unsigned char* __restrict__ codes, int K,
            const float* __restrict__ weff, const float* __restrict__ bq,
            const float* __restrict__ bn, const float* __restrict__ a_ptr,
            float* __restrict__ gates, int accumulate) {
    __shared__ float As[BKK][BM];
    __shared__ float Bs[BKK][BN];

    const int n0 = blockIdx.x * BN;
    const int b0 = blockIdx.y * BM;
    const int tid = threadIdx.x;
    const int tx = tid & 15, ty = tid >> 4;

    unsigned int res[8];
#pragma unroll
    for (int i = 0; i < 8; i++) res[i] = 0u;

    const int rowc = tid >> 1;
    const int kkbase = (tid & 1) * 8;

    for (int m = 0; m < 4; m++) {
        unsigned long long acc2[8][4];
#pragma unroll
        for (int i = 0; i < 8; i++)
#pragma unroll
            for (int j = 0; j < 4; j++) acc2[i][j] = 0ull;  // (+0.0f,+0.0f)

        const float* wm = weff + (size_t)m * K * N4H;
        const int shift = 3 - m;

        for (int kb = 0; kb < K; kb += BKK) {
            __syncthreads();
            // expand bit-plane m of the code tile into As (BKK x BM)
            {
                const unsigned char* src = codes + (size_t)(b0 + rowc) * K + kb + kkbase;
                uint64_t cc = *(const uint64_t*)src;   // 8B aligned
#pragma unroll
                for (int q = 0; q < 8; q++) {
                    unsigned int c = (unsigned int)(cc >> (8 * q)) & 0xffu;
                    As[kkbase + q][rowc] = (float)((c >> shift) & 1u);
                }
            }
            // load weight tile (BKK x BN)
            {
#pragma unroll
                for (int q = 0; q < 2; q++) {
                    int l4 = tid + q * 256;
                    int kk = l4 >> 5;
                    int nq = (l4 & 31) << 2;
                    float4 v = *reinterpret_cast<const float4*>(
                        wm + (size_t)(kb + kk) * N4H + n0 + nq);
                    *reinterpret_cast<float4*>(&Bs[kk][nq]) = v;
                }
            }
            __syncthreads();
#pragma unroll
            for (int k = 0; k < BKK; k++) {
                float a[8], b[8];
                *(float4*)&a[0] = *(float4*)&As[k][ty * 8];
                *(float4*)&a[4] = *(float4*)&As[k][ty * 8 + 4];
                *(float4*)&b[0] = *(float4*)&Bs[k][tx * 8];
                *(float4*)&b[4] = *(float4*)&Bs[k][tx * 8 + 4];
                unsigned long long a2[8], b2[4];
#pragma unroll
                for (int i = 0; i < 8; i++) a2[i] = pk2(a[i], a[i]);
#pragma unroll
                for (int j = 0; j < 4; j++) b2[j] = pk2(b[2 * j], b[2 * j + 1]);
#pragma unroll
                for (int i = 0; i < 8; i++)
#pragma unroll
                    for (int j = 0; j < 4; j++)
                        fma2(acc2[i][j], a2[i], b2[j]);
            }
        }
        // threshold epilogue for plane m -> pack as nibble bits
        const float* bqm = bq + m * N4H + n0 + tx * 8;
        const float* bnm = bn + m * N4H + n0 + tx * 8;
        float fq[8], fn[8];
#pragma unroll
        for (int j = 0; j < 8; j++) { fq[j] = bqm[j]; fn[j] = bnm[j]; }
#pragma unroll
        for (int i = 0; i < 8; i++) {
            float av[8];
#pragma unroll
            for (int j = 0; j < 4; j++) upk2(acc2[i][j], av[2 * j], av[2 * j + 1]);
            unsigned int w = 0;
#pragma unroll
            for (int j = 0; j < 8; j++) {
                float x = __fadd_rn(__fadd_rn(av[j], fq[j]), fn[j]);
                w |= (unsigned int)(x > 0.5f) << (4 * j);
            }
            res[i] += w << shift;
        }
    }

    // beta recombination (sequential m order matching XLA sum over axis 0)
    const float a = a_ptr[0];
    const float twoA = __fmul_rn(a, 2.0f);
    const float beta0 = 8.0f / 15.0f, beta1 = 4.0f / 15.0f;
    const float beta2 = 2.0f / 15.0f, beta3 = 1.0f / 15.0f;
#pragma unroll
    for (int i = 0; i < 8; i++) {
        int row = b0 + ty * 8 + i;
        float* gr = gates + (size_t)row * N4H + n0 + tx * 8;
#pragma unroll
        for (int j = 0; j < 8; j++) {
            unsigned int c = (res[i] >> (4 * j)) & 15u;
            float s = __fmul_rn(beta0, (float)((c >> 3) & 1u));
            s = __fadd_rn(s, __fmul_rn(beta1, (float)((c >> 2) & 1u)));
            s = __fadd_rn(s, __fmul_rn(beta2, (float)((c >> 1) & 1u)));
            s = __fadd_rn(s, __fmul_rn(beta3, (float)(c & 1u)));
            float part = __fsub_rn(__fmul_rn(s, twoA), a);
            gr[j] = accumulate ? __fadd_rn(gr[j], part) : part;
        }
    }
}

// ---------------- elementwise LSTM tail -------------------------------------
__device__ __forceinline__ float clipa(float x, float aa) {
    return fminf(fmaxf(x, -aa), aa);
}
__device__ __forceinline__ float quantf(float x, float r) {
    float xs = __fdiv_rn(x, r);
    xs = fminf(fmaxf(xs, -0.9921875f), 0.9921875f);
    float t = rintf(__fmul_rn(xs, 128.0f));
    return __fmul_rn(__fmul_rn(t, 0.0078125f), r);
}
__device__ __forceinline__ float sigm(float x) {   // XLA logistic expansion
    return __fadd_rn(0.5f, __fmul_rn(0.5f, tanhf(__fmul_rn(0.5f, x))));
}

__global__ void k_tail(const float* __restrict__ gates, const float* __restrict__ cx,
                       float* __restrict__ outh, float* __restrict__ outc,
                       const float* p3, const float* p4, const float* p5,
                       const float* p6, const float* p7, const float* p8,
                       const float* p9, const float* p10, const float* p11) {
    int idx = blockIdx.x * blockDim.x + threadIdx.x;
    if (idx >= B_ * H_) return;
    int b = idx >> 10;
    int h = idx & 1023;
    const float* g = gates + (size_t)b * N4H;
    float gi = g[h];
    float gj = g[H_ + h];
    float gf = g[2 * H_ + h];
    float go = g[3 * H_ + h];

    float a3 = p3[0], a4 = p4[0], a5 = p5[0], a6 = p6[0], a7 = p7[0];
    float a8 = p8[0], a9 = p9[0], a10 = p10[0], a11 = p11[0];

    float fg  = quantf(clipa(sigm(gf), a3), a3);
    float ig  = quantf(clipa(sigm(gi), a4), a4);
    float act = quantf(clipa(tanhf(gj), a5), a5);
    float og  = quantf(clipa(sigm(go), a6), a6);
    float gc  = quantf(clipa(__fmul_rn(cx[idx], fg), a7), a7);
    float ai  = quantf(clipa(__fmul_rn(ig, act), a8), a8);
    float nc  = quantf(clipa(__fadd_rn(gc, ai), a9), a9);
    float acl = quantf(clipa(tanhf(nc), a10), a10);
    float nh  = quantf(clipa(__fmul_rn(acl, og), a11), a11);
    outh[idx] = nh;
    outc[idx] = nc;
}

// ---------------- launch ----------------------------------------------------
extern "C" void kernel_launch(void* const* d_in, const int* in_sizes, int n_in,
                              void* d_out, int out_size) {
    const float* input = (const float*)d_in[0];
    const float* hx    = (const float*)d_in[1];
    const float* cx    = (const float*)d_in[2];
    const float* w_ih  = (const float*)d_in[3];
    const float* w_hh  = (const float*)d_in[4];
    const float* b_ih  = (const float*)d_in[5];
    const float* b_hh  = (const float*)d_in[6];
    const float* a1  = (const float*)d_in[7];
    const float* a3  = (const float*)d_in[8];
    const float* a4  = (const float*)d_in[9];
    const float* a5  = (const float*)d_in[10];
    const float* a6  = (const float*)d_in[11];
    const float* a7  = (const float*)d_in[12];
    const float* a8  = (const float*)d_in[13];
    const float* a9  = (const float*)d_in[14];
    const float* a10 = (const float*)d_in[15];
    const float* a11 = (const float*)d_in[16];
    float* outh = (float*)d_out;
    float* outc = (float*)d_out + (size_t)B_ * H_;

    // JAX key chain (partitionable/fold-like split), computed on host
    uint32_t k1a, k1b, k2a, k2b;
    tf2x32(0u, 42u, 0u, 0u, &k1a, &k1b);   // k1 = split(key(42))[0]
    tf2x32(0u, 42u, 0u, 1u, &k2a, &k2b);   // k2 = split(key(42))[1]
    uint32_t kw1a, kw1b, kb1a, kb1b, kw2a, kw2b, kb2a, kb2b;
    tf2x32(k1a, k1b, 0u, 0u, &kw1a, &kw1b);  // kw for ih
    tf2x32(k1a, k1b, 0u, 1u, &kb1a, &kb1b);  // kb for ih
    tf2x32(k2a, k2b, 0u, 0u, &kw2a, &kw2b);  // kw for hh
    tf2x32(k2a, k2b, 0u, 1u, &kb2a, &kb2b);  // kb for hh

    float *p_weff_ih, *p_weff_hh, *p_bq_ih, *p_bn_ih, *p_bq_hh, *p_bn_hh, *p_gates;
    unsigned char *p_code_in, *p_code_hx;
    cudaGetSymbolAddress((void**)&p_weff_ih, g_weff_ih);
    cudaGetSymbolAddress((void**)&p_weff_hh, g_weff_hh);
    cudaGetSymbolAddress((void**)&p_bq_ih, g_bq_ih);
    cudaGetSymbolAddress((void**)&p_bn_ih, g_bn_ih);
    cudaGetSymbolAddress((void**)&p_bq_hh, g_bq_hh);
    cudaGetSymbolAddress((void**)&p_bn_hh, g_bn_hh);
    cudaGetSymbolAddress((void**)&p_code_in, g_code_in);
    cudaGetSymbolAddress((void**)&p_code_hx, g_code_hx);
    cudaGetSymbolAddress((void**)&p_gates, g_gates);

    const int nwih = M_ * I_ * N4H;
    const int nwhh = M_ * H_ * N4H;
    const int nb = M_ * N4H;

    k_init<<<1, 32>>>();
    k_maxred<<<512, 256>>>(w_ih, nwih, 0);
    k_maxred<<<512, 256>>>(w_hh, nwhh, 1);
    k_maxred<<<64, 256>>>(b_ih, nb, 2);
    k_maxred<<<64, 256>>>(b_hh, nb, 3);

    k_genw<<<(nwih + 255) / 256, 256>>>(w_ih, p_weff_ih, nwih, kw1a, kw1b, 0);
    k_genw<<<(nwhh + 255) / 256, 256>>>(w_hh, p_weff_hh, nwhh, kw2a, kw2b, 1);
    k_genb<<<(nb + 255) / 256, 256>>>(b_ih, p_bq_ih, p_bn_ih, nb, kb1a, kb1b, 2);
    k_genb<<<(nb + 255) / 256, 256>>>(b_hh, p_bq_hh, p_bn_hh, nb, kb2a, kb2b, 3);

    k_code<<<(B_ * I_ + 255) / 256, 256>>>(input, p_code_in, B_ * I_, a1, a1);
    k_code<<<(B_ * H_ + 255) / 256, 256>>>(hx, p_code_hx, B_ * H_, a11, a1);

    dim3 grid(N4H / BN, B_ / BM);
    k_gemm<<<grid, 256>>>(p_code_in, I_, p_weff_ih, p_bq_ih, p_bn_ih, a1, p_gates, 0);
    k_gemm<<<grid, 256>>>(p_code_hx, H_, p_weff_hh, p_bq_hh, p_bn_hh, a11, p_gates, 1);

    k_tail<<<(B_ * H_ + 255) / 256, 256>>>(p_gates, cx, outh, outc,
                                           a3, a4, a5, a6, a7, a8, a9, a10, a11);
}

// round 7
// speedup vs baseline: 1.1562x; 1.1562x over previous
#include <cuda_runtime.h>
#include <cuda_fp16.h>
#include <stdint.h>

#define B_ 4096
#define I_ 256
#define H_ 1024
#define N4H 4096
#define M_ 4
#define EPSM 1e-2f
#define CAPF (1<<20)

// ---------------- device scratch ----------------
__device__ float    g_wf32_ih[M_*N4H*I_];   // [m][n][k] fp32 (fixup)
__device__ float    g_wf32_hh[M_*N4H*H_];
__device__ uint32_t g_w16_ih[M_*N4H*I_];    // [m][n][k] (hi,lo) fp16 pair
__device__ uint32_t g_w16_hh[M_*N4H*H_];
__device__ float g_bq_ih[M_*N4H], g_bn_ih[M_*N4H], g_bq_hh[M_*N4H], g_bn_hh[M_*N4H];
__device__ unsigned char g_code_in[B_*I_], g_code_hx[B_*H_];
__device__ unsigned char g_nib_ih[(size_t)B_*N4H], g_nib_hh[(size_t)B_*N4H];
__device__ float g_max[4];
__device__ int g_cnt[2];
__device__ uint32_t g_list0[CAPF], g_list1[CAPF];

// ---------------- threefry2x32 (JAX exact) ----------------
__host__ __device__ __forceinline__ uint32_t rotl32(uint32_t x, int r) {
    return (x << r) | (x >> (32 - r));
}
__host__ __device__ __forceinline__ void tf2x32(uint32_t k0, uint32_t k1,
                                                uint32_t x0, uint32_t x1,
                                                uint32_t* o0, uint32_t* o1) {
    uint32_t ks0 = k0, ks1 = k1, ks2 = k0 ^ k1 ^ 0x1BD11BDAu;
    x0 += ks0; x1 += ks1;
#define TF_RND(r) { x0 += x1; x1 = rotl32(x1, r); x1 ^= x0; }
    TF_RND(13) TF_RND(15) TF_RND(26) TF_RND(6)
    x0 += ks1; x1 += ks2 + 1u;
    TF_RND(17) TF_RND(29) TF_RND(16) TF_RND(24)
    x0 += ks2; x1 += ks0 + 2u;
    TF_RND(13) TF_RND(15) TF_RND(26) TF_RND(6)
    x0 += ks0; x1 += ks1 + 3u;
    TF_RND(17) TF_RND(29) TF_RND(16) TF_RND(24)
    x0 += ks1; x1 += ks2 + 4u;
    TF_RND(13) TF_RND(15) TF_RND(26) TF_RND(6)
    x0 += ks2; x1 += ks0 + 5u;
#undef TF_RND
    *o0 = x0; *o1 = x1;
}

__device__ __forceinline__ float erfinv_xla(float x) {
    float w = -log1pf(-__fmul_rn(x, x));
    float p;
    if (w < 5.0f) {
        w = w - 2.5f;
        p = 2.81022636e-08f;
        p = fmaf(p, w, 3.43273939e-07f);
        p = fmaf(p, w, -3.5233877e-06f);
        p = fmaf(p, w, -4.39150654e-06f);
        p = fmaf(p, w, 0.00021858087f);
        p = fmaf(p, w, -0.00125372503f);
        p = fmaf(p, w, -0.00417768164f);
        p = fmaf(p, w, 0.246640727f);
        p = fmaf(p, w, 1.50140941f);
    } else {
        w = sqrtf(w) - 3.0f;
        p = -0.000200214257f;
        p = fmaf(p, w, 0.000100950558f);
        p = fmaf(p, w, 0.00134934322f);
        p = fmaf(p, w, -0.00367342844f);
        p = fmaf(p, w, 0.00573950773f);
        p = fmaf(p, w, -0.0076224613f);
        p = fmaf(p, w, 0.00943887047f);
        p = fmaf(p, w, 1.00167406f);
        p = fmaf(p, w, 2.83297682f);
    }
    return __fmul_rn(p, x);
}
__device__ __forceinline__ float normal_from_bits(uint32_t bits) {
    float f = __uint_as_float((bits >> 9) | 0x3f800000u) - 1.0f;
    const float lo = -0.99999994f;
    float u = fmaxf(lo, __fadd_rn(__fmul_rn(f, 2.0f), lo));
    return __fmul_rn(1.41421356f, erfinv_xla(u));
}
__device__ __forceinline__ float quant8(float x) {
    float xs = fminf(fmaxf(x, -0.9921875f), 0.9921875f);
    return __fmul_rn(rintf(__fmul_rn(xs, 128.0f)), 0.0078125f);
}
__device__ __forceinline__ float weff_val(const float* W, int j, uint32_t k0,
                                          uint32_t k1, float wmax) {
    uint32_t o0, o1;
    tf2x32(k0, k1, 0u, (uint32_t)j, &o0, &o1);
    float nrm = normal_from_bits(o0 ^ o1);
    return __fadd_rn(quant8(W[j]), __fmul_rn(__fmul_rn(nrm, wmax), 0.1f));
}

// ---------------- PTX helpers ----------------
__device__ __forceinline__ uint32_t smem_u32(const void* p) {
    uint32_t a;
    asm("{ .reg .u64 t; cvta.to.shared.u64 t, %1; cvt.u32.u64 %0, t; }" : "=r"(a) : "l"(p));
    return a;
}
__device__ __forceinline__ void cpa16(uint32_t dst, const void* src) {
    asm volatile("cp.async.cg.shared.global [%0], [%1], 16;" :: "r"(dst), "l"(src));
}
#define CPA_COMMIT() asm volatile("cp.async.commit_group;" ::: "memory")
#define LDMX4(r, a) asm volatile( \
    "ldmatrix.sync.aligned.m8n8.x4.shared.b16 {%0,%1,%2,%3}, [%4];" \
    : "=r"((r)[0]), "=r"((r)[1]), "=r"((r)[2]), "=r"((r)[3]) : "r"(a))
#define HMMA(c, a, bb0, bb1) asm volatile( \
    "mma.sync.aligned.m16n8k16.row.col.f32.f16.f16.f32 " \
    "{%0,%1,%2,%3},{%4,%5,%6,%7},{%8,%9},{%0,%1,%2,%3};" \
    : "+f"((c)[0]), "+f"((c)[1]), "+f"((c)[2]), "+f"((c)[3]) \
    : "r"((a)[0]), "r"((a)[1]), "r"((a)[2]), "r"((a)[3]), "r"(bb0), "r"(bb1))

// ---------------- small kernels ----------------
__global__ void k_init() {
    if (threadIdx.x < 4) g_max[threadIdx.x] = 0.0f;
    if (threadIdx.x < 2) g_cnt[threadIdx.x] = 0;
}
__global__ void k_maxred(const float* __restrict__ x, int n, int slot) {
    float m = 0.0f;
    for (int i = blockIdx.x * blockDim.x + threadIdx.x; i < n;
         i += gridDim.x * blockDim.x)
        m = fmaxf(m, x[i]);
    for (int o = 16; o; o >>= 1)
        m = fmaxf(m, __shfl_xor_sync(0xffffffffu, m, o));
    if ((threadIdx.x & 31) == 0)
        atomicMax((int*)&g_max[slot], __float_as_int(m));
}
__global__ void k_genb(const float* __restrict__ bsrc, float* __restrict__ bq,
                       float* __restrict__ bn, int n, uint32_t k0, uint32_t k1,
                       int maxslot) {
    int j = blockIdx.x * blockDim.x + threadIdx.x;
    if (j >= n) return;
    uint32_t o0, o1;
    tf2x32(k0, k1, 0u, (uint32_t)j, &o0, &o1);
    float nrm = normal_from_bits(o0 ^ o1);
    bq[j] = quant8(bsrc[j]);
    bn[j] = __fmul_rn(__fmul_rn(nrm, g_max[maxslot]), 0.1f);
}
__global__ void k_code(const float* __restrict__ x, unsigned char* __restrict__ code,
                       int n, const float* __restrict__ aclip,
                       const float* __restrict__ aoff) {
    int i = blockIdx.x * blockDim.x + threadIdx.x;
    if (i >= n) return;
    float ac = aclip[0], off = aoff[0];
    float xc = fminf(fmaxf(x[i], -ac), ac);
    float v01 = __fdiv_rn(__fadd_rn(xc, off), __fmul_rn(ac, 2.0f));
    int v = (int)rintf(__fmul_rn(15.0f, v01));
    code[i] = (unsigned char)(v & 15);
}

// weff gen: fp32 + exact fp16 2-way split, transposed to [m][n][k]
__global__ void k_genw(const float* __restrict__ W, float* __restrict__ wf32,
                       uint32_t* __restrict__ w16, int K,
                       uint32_t key0, uint32_t key1, int maxslot) {
    __shared__ float tf[32][33];
    __shared__ uint32_t th[32][33];
    const int m = blockIdx.z, kk0 = blockIdx.x * 32, nn0 = blockIdx.y * 32;
    const int tx = threadIdx.x, ty = threadIdx.y;
    const float wmax = g_max[maxslot];
    for (int r = ty; r < 32; r += 8) {
        int j = (m * K + kk0 + r) * N4H + nn0 + tx;
        float w = weff_val(W, j, key0, key1, wmax);
        __half hi = __float2half_rn(w);
        float r1 = __fsub_rn(w, __half2float(hi));
        __half lo = __float2half_rn(r1);
        tf[r][tx] = w;
        th[r][tx] = (uint32_t)__half_as_ushort(hi) |
                    ((uint32_t)__half_as_ushort(lo) << 16);
    }
    __syncthreads();
    for (int r = ty; r < 32; r += 8) {
        size_t base = ((size_t)m * N4H + nn0 + r) * K + kk0 + tx;
        wf32[base] = tf[tx][r];
        w16[base] = th[tx][r];
    }
}

// ---------------- HMMA plane GEMM (128x128 tile) ----------------
__global__ __launch_bounds__(256, 2)
void k_mma(const unsigned char* __restrict__ codes, int K,
           const uint32_t* __restrict__ w16, const float* __restrict__ bq,
           const float* __restrict__ bn, unsigned char* __restrict__ nib,
           uint32_t* __restrict__ list, int* __restrict__ cnt) {
    __shared__ __align__(16) char sm[40960];   // 2 bufs x (A 10240 + B 10240)
    const int tid = threadIdx.x, lane = tid & 31, wid = tid >> 5;
    const int n0 = blockIdx.x * 128, b0 = blockIdx.y * 128;
    const int wm = wid & 3, wn = wid >> 2;
    const int NC = (2 * K) / 32;
    const uint32_t sbase = smem_u32(sm);
    uint32_t sA[2] = {sbase, sbase + 20480};
    uint32_t sB[2] = {sbase + 10240, sbase + 30720};

    const int arow = (lane & 7) + ((lane >> 3) & 1) * 8;
    const int akg = (lane >> 4) & 1;
    const int brow = (lane & 7) + ((lane >> 4) & 1) * 8;
    const int bkg = (lane >> 3) & 1;
    const int erow = tid >> 1, eseg = tid & 1;     // A-expansion mapping

    uint32_t nbacc[2][8];
#pragma unroll
    for (int i = 0; i < 2; i++)
#pragma unroll
        for (int j = 0; j < 8; j++) nbacc[i][j] = 0u;

    for (int m = 0; m < 4; m++) {
        const int shift = 3 - m;
        const uint32_t* wmp = w16 + (size_t)m * N4H * K;
        float acc[2][8][4];
#pragma unroll
        for (int i = 0; i < 2; i++)
#pragma unroll
            for (int j = 0; j < 8; j++)
#pragma unroll
                for (int q = 0; q < 4; q++) acc[i][j][q] = 0.0f;

        auto load = [&](int c) {
            int buf = c & 1;
            int kb2 = c * 16;  // original-k index base (16 per chunk)
            // A bit-plane expansion (dup each bit to hi/lo K' pair)
            {
                const unsigned char* cp =
                    codes + (size_t)(b0 + erow) * K + kb2 + eseg * 8;
                uint64_t cc = *(const uint64_t*)cp;
                uint32_t v[8];
#pragma unroll
                for (int q = 0; q < 8; q++)
                    v[q] = ((((uint32_t)(cc >> (8 * q))) >> shift) & 1u)
                               ? 0x3C003C00u : 0u;
                char* dst = sm + (buf ? 20480 : 0) + erow * 80 + eseg * 32;
                *(uint4*)dst = make_uint4(v[0], v[1], v[2], v[3]);
                *(uint4*)(dst + 16) = make_uint4(v[4], v[5], v[6], v[7]);
            }
            // B tile: 128 n-rows x 16 uint32 via cp.async
#pragma unroll
            for (int q = 0; q < 2; q++) {
                int idx = tid + q * 256;
                int row = idx >> 2, part = idx & 3;
                const uint32_t* g =
                    wmp + (size_t)(n0 + row) * K + kb2 + part * 4;
                cpa16(sB[buf] + row * 80 + part * 16, g);
            }
            CPA_COMMIT();
        };

        load(0);
        for (int c = 0; c < NC; c++) {
            if (c + 1 < NC) {
                load(c + 1);
                asm volatile("cp.async.wait_group 1;" ::: "memory");
            } else {
                asm volatile("cp.async.wait_group 0;" ::: "memory");
            }
            __syncthreads();
            int buf = c & 1;
#pragma unroll
            for (int ks = 0; ks < 2; ks++) {
                uint32_t aF[2][4], bF[4][4];
#pragma unroll
                for (int mi = 0; mi < 2; mi++)
                    LDMX4(aF[mi], sA[buf] + (wm * 32 + mi * 16 + arow) * 80 +
                                      ks * 32 + akg * 16);
#pragma unroll
                for (int nj = 0; nj < 4; nj++)
                    LDMX4(bF[nj], sB[buf] + (wn * 64 + nj * 16 + brow) * 80 +
                                      ks * 32 + bkg * 16);
#pragma unroll
                for (int mi = 0; mi < 2; mi++)
#pragma unroll
                    for (int ni = 0; ni < 8; ni++)
                        HMMA(acc[mi][ni], aF[mi], bF[ni >> 1][(ni & 1) * 2],
                             bF[ni >> 1][(ni & 1) * 2 + 1]);
            }
            __syncthreads();
        }
        // plane epilogue: threshold + margin flag + nibble pack
#pragma unroll
        for (int mi = 0; mi < 2; mi++)
#pragma unroll
            for (int ni = 0; ni < 8; ni++) {
                int n = n0 + wn * 64 + ni * 8 + (lane & 3) * 2;
                float2 bqv = *(const float2*)&bq[m * N4H + n];
                float2 bnv = *(const float2*)&bn[m * N4H + n];
                int r0 = b0 + wm * 32 + mi * 16 + (lane >> 2);
                float x[4];
                x[0] = __fadd_rn(__fadd_rn(acc[mi][ni][0], bqv.x), bnv.x);
                x[1] = __fadd_rn(__fadd_rn(acc[mi][ni][1], bqv.y), bnv.y);
                x[2] = __fadd_rn(__fadd_rn(acc[mi][ni][2], bqv.x), bnv.x);
                x[3] = __fadd_rn(__fadd_rn(acc[mi][ni][3], bqv.y), bnv.y);
                uint32_t nb = 0;
#pragma unroll
                for (int e = 0; e < 4; e++) {
                    int rb = (e < 2) ? r0 : r0 + 8;
                    int nn = n + (e & 1);
                    nb |= (uint32_t)(x[e] > 0.5f) << (8 * e + shift);
                    if (fabsf(x[e] - 0.5f) < EPSM) {
                        int idx = atomicAdd(cnt, 1);
                        if (idx < CAPF)
                            list[idx] = ((uint32_t)rb << 12) | (uint32_t)nn;
                    }
                }
                nbacc[mi][ni] |= nb;
            }
    }
    // final nibble store (2 bytes per store)
#pragma unroll
    for (int mi = 0; mi < 2; mi++)
#pragma unroll
        for (int ni = 0; ni < 8; ni++) {
            int n = n0 + wn * 64 + ni * 8 + (lane & 3) * 2;
            int r0 = b0 + wm * 32 + mi * 16 + (lane >> 2);
            uint32_t v = nbacc[mi][ni];
            *(unsigned short*)&nib[(size_t)r0 * N4H + n] =
                (unsigned short)(v & 0xFFFFu);
            *(unsigned short*)&nib[(size_t)(r0 + 8) * N4H + n] =
                (unsigned short)(v >> 16);
        }
}

// ---------------- exact fixup (ascending-k fp32 chain) ----------------
__global__ void k_fixup(const unsigned char* __restrict__ codes, int K,
                        const float* __restrict__ wf32,
                        const float* __restrict__ bq, const float* __restrict__ bn,
                        unsigned char* __restrict__ nib,
                        const uint32_t* __restrict__ list,
                        const int* __restrict__ cnt) {
    __shared__ float terms[8][1024];
    int wid = threadIdx.x >> 5, lid = threadIdx.x & 31;
    int nwarp = gridDim.x * 8;
    int total = min(*cnt, CAPF);
    for (int e = blockIdx.x * 8 + wid; e < total; e += nwarp) {
        uint32_t ent = list[e];
        int b = ent >> 12, n = ent & 0xFFF;
        unsigned char v = 0;
        for (int m = 0; m < 4; m++) {
            int shift = 3 - m;
            const float* wr = wf32 + ((size_t)m * N4H + n) * K;
            for (int k = lid; k < K; k += 32) {
                int bit = (codes[(size_t)b * K + k] >> shift) & 1;
                terms[wid][k] = bit ? wr[k] : 0.0f;
            }
            __syncwarp();
            if (lid == 0) {
                float acc = 0.0f;
                for (int k = 0; k < K; k++) {
                    if (terms[wid][k] != 0.0f)
                        acc = __fadd_rn(acc, terms[wid][k]);
                }
                float x = __fadd_rn(__fadd_rn(acc, bq[m * N4H + n]),
                                    bn[m * N4H + n]);
                v |= (unsigned char)((x > 0.5f) << shift);
            }
            __syncwarp();
        }
        if (lid == 0) nib[(size_t)b * N4H + n] = v;
    }
}

// ---------------- fused recombine + LSTM tail ----------------
__device__ __forceinline__ float clipa(float x, float aa) {
    return fminf(fmaxf(x, -aa), aa);
}
__device__ __forceinline__ float quantf(float x, float r) {
    float xs = fminf(fmaxf(__fdiv_rn(x, r), -0.9921875f), 0.9921875f);
    return __fmul_rn(__fmul_rn(rintf(__fmul_rn(xs, 128.0f)), 0.0078125f), r);
}
__device__ __forceinline__ float sigm(float x) {
    return __fadd_rn(0.5f, __fmul_rn(0.5f, tanhf(__fmul_rn(0.5f, x))));
}
__device__ __forceinline__ float partv(unsigned char c, float a) {
    const float c0 = 8.0f / 15.0f, c1 = 4.0f / 15.0f, c2 = 2.0f / 15.0f,
                c3 = 1.0f / 15.0f;
    float s = __fmul_rn(c0, (float)((c >> 3) & 1u));
    s = __fadd_rn(s, __fmul_rn(c1, (float)((c >> 2) & 1u)));
    s = __fadd_rn(s, __fmul_rn(c2, (float)((c >> 1) & 1u)));
    s = __fadd_rn(s, __fmul_rn(c3, (float)(c & 1u)));
    return __fsub_rn(__fmul_rn(s, __fmul_rn(a, 2.0f)), a);
}

__global__ void k_tail(const float* __restrict__ cx, float* __restrict__ outh,
                       float* __restrict__ outc, const float* p1, const float* p3,
                       const float* p4, const float* p5, const float* p6,
                       const float* p7, const float* p8, const float* p9,
                       const float* p10, const float* p11) {
    int idx = blockIdx.x * blockDim.x + threadIdx.x;
    if (idx >= B_ * H_) return;
    int b = idx >> 10, h = idx & 1023;
    float a1 = p1[0], a11v = p11[0];
    const unsigned char* n1 = g_nib_ih + (size_t)b * N4H;
    const unsigned char* n2 = g_nib_hh + (size_t)b * N4H;
    float gi = __fadd_rn(partv(n1[h], a1), partv(n2[h], a11v));
    float gj = __fadd_rn(partv(n1[H_ + h], a1), partv(n2[H_ + h], a11v));
    float gf = __fadd_rn(partv(n1[2 * H_ + h], a1), partv(n2[2 * H_ + h], a11v));
    float go = __fadd_rn(partv(n1[3 * H_ + h], a1), partv(n2[3 * H_ + h], a11v));
    float a3 = p3[0], a4 = p4[0], a5 = p5[0], a6 = p6[0], a7 = p7[0];
    float a8 = p8[0], a9 = p9[0], a10 = p10[0];
    float fg  = quantf(clipa(sigm(gf), a3), a3);
    float ig  = quantf(clipa(sigm(gi), a4), a4);
    float act = quantf(clipa(tanhf(gj), a5), a5);
    float og  = quantf(clipa(sigm(go), a6), a6);
    float gc  = quantf(clipa(__fmul_rn(cx[idx], fg), a7), a7);
    float ai  = quantf(clipa(__fmul_rn(ig, act), a8), a8);
    float nc  = quantf(clipa(__fadd_rn(gc, ai), a9), a9);
    float acl = quantf(clipa(tanhf(nc), a10), a10);
    outh[idx] = quantf(clipa(__fmul_rn(acl, og), a11v), a11v);
    outc[idx] = nc;
}

// ---------------- launch ----------------
extern "C" void kernel_launch(void* const* d_in, const int* in_sizes, int n_in,
                              void* d_out, int out_size) {
    const float* input = (const float*)d_in[0];
    const float* hx    = (const float*)d_in[1];
    const float* cx    = (const float*)d_in[2];
    const float* w_ih  = (const float*)d_in[3];
    const float* w_hh  = (const float*)d_in[4];
    const float* b_ih  = (const float*)d_in[5];
    const float* b_hh  = (const float*)d_in[6];
    const float* a1  = (const float*)d_in[7];
    const float* a3  = (const float*)d_in[8];
    const float* a4  = (const float*)d_in[9];
    const float* a5  = (const float*)d_in[10];
    const float* a6  = (const float*)d_in[11];
    const float* a7  = (const float*)d_in[12];
    const float* a8  = (const float*)d_in[13];
    const float* a9  = (const float*)d_in[14];
    const float* a10 = (const float*)d_in[15];
    const float* a11 = (const float*)d_in[16];
    float* outh = (float*)d_out;
    float* outc = (float*)d_out + (size_t)B_ * H_;

    uint32_t k1a, k1b, k2a, k2b;
    tf2x32(0u, 42u, 0u, 0u, &k1a, &k1b);
    tf2x32(0u, 42u, 0u, 1u, &k2a, &k2b);
    uint32_t kw1a, kw1b, kb1a, kb1b, kw2a, kw2b, kb2a, kb2b;
    tf2x32(k1a, k1b, 0u, 0u, &kw1a, &kw1b);
    tf2x32(k1a, k1b, 0u, 1u, &kb1a, &kb1b);
    tf2x32(k2a, k2b, 0u, 0u, &kw2a, &kw2b);
    tf2x32(k2a, k2b, 0u, 1u, &kb2a, &kb2b);

    float *pwf_ih, *pwf_hh, *pbq_ih, *pbn_ih, *pbq_hh, *pbn_hh;
    uint32_t *pw16_ih, *pw16_hh, *plist0, *plist1;
    unsigned char *pcode_in, *pcode_hx, *pnib_ih, *pnib_hh;
    int* pcnt;
    cudaGetSymbolAddress((void**)&pwf_ih, g_wf32_ih);
    cudaGetSymbolAddress((void**)&pwf_hh, g_wf32_hh);
    cudaGetSymbolAddress((void**)&pw16_ih, g_w16_ih);
    cudaGetSymbolAddress((void**)&pw16_hh, g_w16_hh);
    cudaGetSymbolAddress((void**)&pbq_ih, g_bq_ih);
    cudaGetSymbolAddress((void**)&pbn_ih, g_bn_ih);
    cudaGetSymbolAddress((void**)&pbq_hh, g_bq_hh);
    cudaGetSymbolAddress((void**)&pbn_hh, g_bn_hh);
    cudaGetSymbolAddress((void**)&pcode_in, g_code_in);
    cudaGetSymbolAddress((void**)&pcode_hx, g_code_hx);
    cudaGetSymbolAddress((void**)&pnib_ih, g_nib_ih);
    cudaGetSymbolAddress((void**)&pnib_hh, g_nib_hh);
    cudaGetSymbolAddress((void**)&plist0, g_list0);
    cudaGetSymbolAddress((void**)&plist1, g_list1);
    cudaGetSymbolAddress((void**)&pcnt, g_cnt);

    const int nb = M_ * N4H;
    k_init<<<1, 32>>>();
    k_maxred<<<512, 256>>>(w_ih, M_ * I_ * N4H, 0);
    k_maxred<<<512, 256>>>(w_hh, M_ * H_ * N4H, 1);
    k_maxred<<<64, 256>>>(b_ih, nb, 2);
    k_maxred<<<64, 256>>>(b_hh, nb, 3);

    dim3 tb8(32, 8);
    k_genw<<<dim3(I_ / 32, N4H / 32, M_), tb8>>>(w_ih, pwf_ih, pw16_ih, I_,
                                                 kw1a, kw1b, 0);
    k_genw<<<dim3(H_ / 32, N4H / 32, M_), tb8>>>(w_hh, pwf_hh, pw16_hh, H_,
                                                 kw2a, kw2b, 1);
    k_genb<<<(nb + 255) / 256, 256>>>(b_ih, pbq_ih, pbn_ih, nb, kb1a, kb1b, 2);
    k_genb<<<(nb + 255) / 256, 256>>>(b_hh, pbq_hh, pbn_hh, nb, kb2a, kb2b, 3);
    k_code<<<(B_ * I_ + 255) / 256, 256>>>(input, pcode_in, B_ * I_, a1, a1);
    k_code<<<(B_ * H_ + 255) / 256, 256>>>(hx, pcode_hx, B_ * H_, a11, a1);

    dim3 grid(N4H / 128, B_ / 128);
    k_mma<<<grid, 256>>>(pcode_in, I_, pw16_ih, pbq_ih, pbn_ih, pnib_ih,
                         plist0, pcnt);
    k_mma<<<grid, 256>>>(pcode_hx, H_, pw16_hh, pbq_hh, pbn_hh, pnib_hh,
                         plist1, pcnt + 1);

    k_fixup<<<512, 256>>>(pcode_in, I_, pwf_ih, pbq_ih, pbn_ih, pnib_ih,
                          plist0, pcnt);
    k_fixup<<<512, 256>>>(pcode_hx, H_, pwf_hh, pbq_hh, pbn_hh, pnib_hh,
                          plist1, pcnt + 1);

    k_tail<<<(B_ * H_ + 255) / 256, 256>>>(cx, outh, outc, a1, a3, a4, a5, a6,
                                           a7, a8, a9, a10, a11);
}

// round 8
// speedup vs baseline: 1.6502x; 1.4273x over previous
#include <cuda_runtime.h>
#include <cuda_fp16.h>
#include <stdint.h>

#define B_ 4096
#define I_ 256
#define H_ 1024
#define N4H 4096
#define M_ 4
#define EPSM 1e-2f
#define CAPF (1<<20)
#define BN_SZ ((size_t)B_*N4H)

// ---------------- device scratch ----------------
__device__ float    g_wf32_ih[M_*N4H*I_];
__device__ float    g_wf32_hh[M_*N4H*H_];
__device__ uint32_t g_w16_ih[M_*N4H*I_];
__device__ uint32_t g_w16_hh[M_*N4H*H_];
__device__ float g_bq_ih[M_*N4H], g_bn_ih[M_*N4H], g_bq_hh[M_*N4H], g_bn_hh[M_*N4H];
__device__ unsigned char g_code_in[B_*I_], g_code_hx[B_*H_];
__device__ unsigned char g_nib_ih[BN_SZ];
__device__ unsigned char g_pb_hh[4*BN_SZ];     // per-plane decision bytes (hh)
__device__ float g_max[4];
__device__ int g_cnt[2];
__device__ int g_done[8];                      // ih planes 0-3, hh planes 4-7
__device__ uint32_t g_list0[CAPF], g_list1[CAPF];

// ---------------- threefry2x32 (JAX exact) ----------------
__host__ __device__ __forceinline__ uint32_t rotl32(uint32_t x, int r) {
    return (x << r) | (x >> (32 - r));
}
__host__ __device__ __forceinline__ void tf2x32(uint32_t k0, uint32_t k1,
                                                uint32_t x0, uint32_t x1,
                                                uint32_t* o0, uint32_t* o1) {
    uint32_t ks0 = k0, ks1 = k1, ks2 = k0 ^ k1 ^ 0x1BD11BDAu;
    x0 += ks0; x1 += ks1;
#define TF_RND(r) { x0 += x1; x1 = rotl32(x1, r); x1 ^= x0; }
    TF_RND(13) TF_RND(15) TF_RND(26) TF_RND(6)
    x0 += ks1; x1 += ks2 + 1u;
    TF_RND(17) TF_RND(29) TF_RND(16) TF_RND(24)
    x0 += ks2; x1 += ks0 + 2u;
    TF_RND(13) TF_RND(15) TF_RND(26) TF_RND(6)
    x0 += ks0; x1 += ks1 + 3u;
    TF_RND(17) TF_RND(29) TF_RND(16) TF_RND(24)
    x0 += ks1; x1 += ks2 + 4u;
    TF_RND(13) TF_RND(15) TF_RND(26) TF_RND(6)
    x0 += ks2; x1 += ks0 + 5u;
#undef TF_RND
    *o0 = x0; *o1 = x1;
}

__device__ __forceinline__ float erfinv_xla(float x) {
    float w = -log1pf(-__fmul_rn(x, x));
    float p;
    if (w < 5.0f) {
        w = w - 2.5f;
        p = 2.81022636e-08f;
        p = fmaf(p, w, 3.43273939e-07f);
        p = fmaf(p, w, -3.5233877e-06f);
        p = fmaf(p, w, -4.39150654e-06f);
        p = fmaf(p, w, 0.00021858087f);
        p = fmaf(p, w, -0.00125372503f);
        p = fmaf(p, w, -0.00417768164f);
        p = fmaf(p, w, 0.246640727f);
        p = fmaf(p, w, 1.50140941f);
    } else {
        w = sqrtf(w) - 3.0f;
        p = -0.000200214257f;
        p = fmaf(p, w, 0.000100950558f);
        p = fmaf(p, w, 0.00134934322f);
        p = fmaf(p, w, -0.00367342844f);
        p = fmaf(p, w, 0.00573950773f);
        p = fmaf(p, w, -0.0076224613f);
        p = fmaf(p, w, 0.00943887047f);
        p = fmaf(p, w, 1.00167406f);
        p = fmaf(p, w, 2.83297682f);
    }
    return __fmul_rn(p, x);
}
__device__ __forceinline__ float normal_from_bits(uint32_t bits) {
    float f = __uint_as_float((bits >> 9) | 0x3f800000u) - 1.0f;
    const float lo = -0.99999994f;
    float u = fmaxf(lo, __fadd_rn(__fmul_rn(f, 2.0f), lo));
    return __fmul_rn(1.41421356f, erfinv_xla(u));
}
__device__ __forceinline__ float quant8(float x) {
    float xs = fminf(fmaxf(x, -0.9921875f), 0.9921875f);
    return __fmul_rn(rintf(__fmul_rn(xs, 128.0f)), 0.0078125f);
}
__device__ __forceinline__ float weff_val(const float* W, int j, uint32_t k0,
                                          uint32_t k1, float wmax) {
    uint32_t o0, o1;
    tf2x32(k0, k1, 0u, (uint32_t)j, &o0, &o1);
    float nrm = normal_from_bits(o0 ^ o1);
    return __fadd_rn(quant8(W[j]), __fmul_rn(__fmul_rn(nrm, wmax), 0.1f));
}

// ---------------- PTX helpers ----------------
__device__ __forceinline__ uint32_t smem_u32(const void* p) {
    uint32_t a;
    asm("{ .reg .u64 t; cvta.to.shared.u64 t, %1; cvt.u32.u64 %0, t; }" : "=r"(a) : "l"(p));
    return a;
}
__device__ __forceinline__ void cpa16(uint32_t dst, const void* src) {
    asm volatile("cp.async.cg.shared.global [%0], [%1], 16;" :: "r"(dst), "l"(src));
}
#define CPA_COMMIT() asm volatile("cp.async.commit_group;" ::: "memory")
#define LDMX4(r, a) asm volatile( \
    "ldmatrix.sync.aligned.m8n8.x4.shared.b16 {%0,%1,%2,%3}, [%4];" \
    : "=r"((r)[0]), "=r"((r)[1]), "=r"((r)[2]), "=r"((r)[3]) : "r"(a))
#define HMMA(c, a, bb0, bb1) asm volatile( \
    "mma.sync.aligned.m16n8k16.row.col.f32.f16.f16.f32 " \
    "{%0,%1,%2,%3},{%4,%5,%6,%7},{%8,%9},{%0,%1,%2,%3};" \
    : "+f"((c)[0]), "+f"((c)[1]), "+f"((c)[2]), "+f"((c)[3]) \
    : "r"((a)[0]), "r"((a)[1]), "r"((a)[2]), "r"((a)[3]), "r"(bb0), "r"(bb1))

__device__ __forceinline__ void spinwait(int slot, int target) {
    if (threadIdx.x == 0) {
        while (*(volatile int*)&g_done[slot] < target) __nanosleep(200);
        __threadfence();
    }
    __syncthreads();
}

// ---------------- small kernels ----------------
__global__ void k_init() {
    if (threadIdx.x < 4) g_max[threadIdx.x] = 0.0f;
    if (threadIdx.x < 2) g_cnt[threadIdx.x] = 0;
    if (threadIdx.x < 8) g_done[threadIdx.x] = 0;
}
__global__ void k_maxred(const float* __restrict__ x, int n, int slot) {
    float m = 0.0f;
    for (int i = blockIdx.x * blockDim.x + threadIdx.x; i < n;
         i += gridDim.x * blockDim.x)
        m = fmaxf(m, x[i]);
    for (int o = 16; o; o >>= 1)
        m = fmaxf(m, __shfl_xor_sync(0xffffffffu, m, o));
    if ((threadIdx.x & 31) == 0)
        atomicMax((int*)&g_max[slot], __float_as_int(m));
}
__global__ void k_genb(const float* __restrict__ bsrc, float* __restrict__ bq,
                       float* __restrict__ bn, int n, uint32_t k0, uint32_t k1,
                       int maxslot) {
    int j = blockIdx.x * blockDim.x + threadIdx.x;
    if (j >= n) return;
    uint32_t o0, o1;
    tf2x32(k0, k1, 0u, (uint32_t)j, &o0, &o1);
    float nrm = normal_from_bits(o0 ^ o1);
    bq[j] = quant8(bsrc[j]);
    bn[j] = __fmul_rn(__fmul_rn(nrm, g_max[maxslot]), 0.1f);
}
__global__ void k_code(const float* __restrict__ x, unsigned char* __restrict__ code,
                       int n, const float* __restrict__ aclip,
                       const float* __restrict__ aoff) {
    int i = blockIdx.x * blockDim.x + threadIdx.x;
    if (i >= n) return;
    float ac = aclip[0], off = aoff[0];
    float xc = fminf(fmaxf(x[i], -ac), ac);
    float v01 = __fdiv_rn(__fadd_rn(xc, off), __fmul_rn(ac, 2.0f));
    int v = (int)rintf(__fmul_rn(15.0f, v01));
    code[i] = (unsigned char)(v & 15);
}

// ---------------- role: gen one 32k x 32n tile of plane m ----------------
__device__ void do_gen(const float* __restrict__ W, float* __restrict__ wf32,
                       uint32_t* __restrict__ w16, int K,
                       uint32_t key0, uint32_t key1, int maxslot,
                       int m, int kt, int nt, int doneslot) {
    __shared__ float tf[32][33];
    __shared__ uint32_t th[32][33];
    const int tid = threadIdx.x;
    const int kk0 = kt * 32, nn0 = nt * 32;
    const int tx = tid & 31, ty = tid >> 5;
    const float wmax = g_max[maxslot];
#pragma unroll
    for (int r = ty; r < 32; r += 8) {
        int j = (m * K + kk0 + r) * N4H + nn0 + tx;
        float w = weff_val(W, j, key0, key1, wmax);
        __half hi = __float2half_rn(w);
        float r1 = __fsub_rn(w, __half2float(hi));
        __half lo = __float2half_rn(r1);
        tf[r][tx] = w;
        th[r][tx] = (uint32_t)__half_as_ushort(hi) |
                    ((uint32_t)__half_as_ushort(lo) << 16);
    }
    __syncthreads();
#pragma unroll
    for (int r = ty; r < 32; r += 8) {
        size_t base = ((size_t)m * N4H + nn0 + r) * K + kk0 + tx;
        wf32[base] = tf[tx][r];
        w16[base] = th[tx][r];
    }
    __threadfence();
    __syncthreads();
    if (tid == 0) atomicAdd(&g_done[doneslot], 1);
}

// ---------------- role: HMMA 128x128 tile, planes [mstart,mend) --------------
__device__ void do_mma(const unsigned char* __restrict__ codes, int K,
                       const uint32_t* __restrict__ w16,
                       const float* __restrict__ bq, const float* __restrict__ bn,
                       unsigned char* __restrict__ nib,   // nibble out (or null)
                       unsigned char* __restrict__ pb,    // plane-byte out (or null)
                       uint32_t* __restrict__ list, int* __restrict__ cnt,
                       int mstart, int mend, int slot0, int target,
                       int n0, int b0) {
    __shared__ __align__(16) char sm[40960];
    const int tid = threadIdx.x, lane = tid & 31, wid = tid >> 5;
    const int wm = wid & 3, wn = wid >> 2;
    const int NC = (2 * K) / 32;
    const uint32_t sbase = smem_u32(sm);
    uint32_t sA[2] = {sbase, sbase + 20480};
    uint32_t sB[2] = {sbase + 10240, sbase + 30720};

    const int arow = (lane & 7) + ((lane >> 3) & 1) * 8;
    const int akg = (lane >> 4) & 1;
    const int brow = (lane & 7) + ((lane >> 4) & 1) * 8;
    const int bkg = (lane >> 3) & 1;
    const int erow = tid >> 1, eseg = tid & 1;

    uint32_t nbacc[2][8];
#pragma unroll
    for (int i = 0; i < 2; i++)
#pragma unroll
        for (int j = 0; j < 8; j++) nbacc[i][j] = 0u;

    for (int m = mstart; m < mend; m++) {
        spinwait(slot0 + m, target);
        const int shift = 3 - m;
        const uint32_t* wmp = w16 + (size_t)m * N4H * K;
        float acc[2][8][4];
#pragma unroll
        for (int i = 0; i < 2; i++)
#pragma unroll
            for (int j = 0; j < 8; j++)
#pragma unroll
                for (int q = 0; q < 4; q++) acc[i][j][q] = 0.0f;

        auto load = [&](int c) {
            int buf = c & 1;
            int kb2 = c * 16;
            {
                const unsigned char* cp =
                    codes + (size_t)(b0 + erow) * K + kb2 + eseg * 8;
                uint64_t cc = *(const uint64_t*)cp;
                uint32_t v[8];
#pragma unroll
                for (int q = 0; q < 8; q++)
                    v[q] = ((((uint32_t)(cc >> (8 * q))) >> shift) & 1u)
                               ? 0x3C003C00u : 0u;
                char* dst = sm + (buf ? 20480 : 0) + erow * 80 + eseg * 32;
                *(uint4*)dst = make_uint4(v[0], v[1], v[2], v[3]);
                *(uint4*)(dst + 16) = make_uint4(v[4], v[5], v[6], v[7]);
            }
#pragma unroll
            for (int q = 0; q < 2; q++) {
                int idx = tid + q * 256;
                int row = idx >> 2, part = idx & 3;
                const uint32_t* g = wmp + (size_t)(n0 + row) * K + kb2 + part * 4;
                cpa16(sB[buf] + row * 80 + part * 16, g);
            }
            CPA_COMMIT();
        };

        load(0);
        for (int c = 0; c < NC; c++) {
            if (c + 1 < NC) {
                load(c + 1);
                asm volatile("cp.async.wait_group 1;" ::: "memory");
            } else {
                asm volatile("cp.async.wait_group 0;" ::: "memory");
            }
            __syncthreads();
            int buf = c & 1;
#pragma unroll
            for (int ks = 0; ks < 2; ks++) {
                uint32_t aF[2][4], bF[4][4];
#pragma unroll
                for (int mi = 0; mi < 2; mi++)
                    LDMX4(aF[mi], sA[buf] + (wm * 32 + mi * 16 + arow) * 80 +
                                      ks * 32 + akg * 16);
#pragma unroll
                for (int nj = 0; nj < 4; nj++)
                    LDMX4(bF[nj], sB[buf] + (wn * 64 + nj * 16 + brow) * 80 +
                                      ks * 32 + bkg * 16);
#pragma unroll
                for (int mi = 0; mi < 2; mi++)
#pragma unroll
                    for (int ni = 0; ni < 8; ni++)
                        HMMA(acc[mi][ni], aF[mi], bF[ni >> 1][(ni & 1) * 2],
                             bF[ni >> 1][(ni & 1) * 2 + 1]);
            }
            __syncthreads();
        }
        // epilogue: threshold + margin flag; nibble-accumulate or plane bytes
#pragma unroll
        for (int mi = 0; mi < 2; mi++)
#pragma unroll
            for (int ni = 0; ni < 8; ni++) {
                int n = n0 + wn * 64 + ni * 8 + (lane & 3) * 2;
                float2 bqv = *(const float2*)&bq[m * N4H + n];
                float2 bnv = *(const float2*)&bn[m * N4H + n];
                int r0 = b0 + wm * 32 + mi * 16 + (lane >> 2);
                float x[4];
                x[0] = __fadd_rn(__fadd_rn(acc[mi][ni][0], bqv.x), bnv.x);
                x[1] = __fadd_rn(__fadd_rn(acc[mi][ni][1], bqv.y), bnv.y);
                x[2] = __fadd_rn(__fadd_rn(acc[mi][ni][2], bqv.x), bnv.x);
                x[3] = __fadd_rn(__fadd_rn(acc[mi][ni][3], bqv.y), bnv.y);
#pragma unroll
                for (int e = 0; e < 4; e++) {
                    int rb = (e < 2) ? r0 : r0 + 8;
                    int nn = n + (e & 1);
                    int bit = x[e] > 0.5f;
                    if (nib) nbacc[mi][ni] |= (uint32_t)bit << (8 * e + shift);
                    else pb[(size_t)m * BN_SZ + (size_t)rb * N4H + nn] =
                             (unsigned char)bit;
                    if (fabsf(x[e] - 0.5f) < EPSM) {
                        int idx = atomicAdd(cnt, 1);
                        if (idx < CAPF)
                            list[idx] = ((uint32_t)rb << 12) | (uint32_t)nn;
                    }
                }
            }
    }
    if (nib) {
#pragma unroll
        for (int mi = 0; mi < 2; mi++)
#pragma unroll
            for (int ni = 0; ni < 8; ni++) {
                int n = n0 + wn * 64 + ni * 8 + (lane & 3) * 2;
                int r0 = b0 + wm * 32 + mi * 16 + (lane >> 2);
                uint32_t v = nbacc[mi][ni];
                *(unsigned short*)&nib[(size_t)r0 * N4H + n] =
                    (unsigned short)(v & 0xFFFFu);
                *(unsigned short*)&nib[(size_t)(r0 + 8) * N4H + n] =
                    (unsigned short)(v >> 16);
            }
    }
}

// ---------------- fused pipeline kernel ----------------
// bid layout (monotone dispatch => all spin deps have strictly lower bids):
// [0,4096)      gen_ih planes 0-3 (1024 each)
// [4096,12288)  gen_hh planes 0-1 (4096 each)
// [12288,13312) mma_ih (4-plane loop, nibble)
// [13312,14336) mma_hh plane 0
// [14336,18432) gen_hh plane 2
// [18432,19456) mma_hh plane 1
// [19456,23552) gen_hh plane 3
// [23552,24576) mma_hh plane 2
// [24576,25600) mma_hh plane 3
__global__ __launch_bounds__(256, 2)
void k_fused(const float* __restrict__ w_ih, const float* __restrict__ w_hh,
             uint32_t kw1a, uint32_t kw1b, uint32_t kw2a, uint32_t kw2b) {
    const int bid = blockIdx.x;
    if (bid < 4096) {
        int m = bid >> 10, r = bid & 1023;
        do_gen(w_ih, g_wf32_ih, g_w16_ih, I_, kw1a, kw1b, 0,
               m, r & 7, r >> 3, m);
    } else if (bid < 12288) {
        int lb = bid - 4096;
        int m = lb >> 12, r = lb & 4095;
        do_gen(w_hh, g_wf32_hh, g_w16_hh, H_, kw2a, kw2b, 1,
               m, r & 31, r >> 5, 4 + m);
    } else if (bid < 13312) {
        int lb = bid - 12288;
        do_mma(g_code_in, I_, g_w16_ih, g_bq_ih, g_bn_ih, g_nib_ih, 0,
               g_list0, &g_cnt[0], 0, 4, 0, 1024,
               (lb & 31) * 128, (lb >> 5) * 128);
    } else if (bid < 14336) {
        int lb = bid - 13312;
        do_mma(g_code_hx, H_, g_w16_hh, g_bq_hh, g_bn_hh, 0, g_pb_hh,
               g_list1, &g_cnt[1], 0, 1, 4, 4096,
               (lb & 31) * 128, (lb >> 5) * 128);
    } else if (bid < 18432) {
        int r = bid - 14336;
        do_gen(w_hh, g_wf32_hh, g_w16_hh, H_, kw2a, kw2b, 1,
               2, r & 31, r >> 5, 6);
    } else if (bid < 19456) {
        int lb = bid - 18432;
        do_mma(g_code_hx, H_, g_w16_hh, g_bq_hh, g_bn_hh, 0, g_pb_hh,
               g_list1, &g_cnt[1], 1, 2, 4, 4096,
               (lb & 31) * 128, (lb >> 5) * 128);
    } else if (bid < 23552) {
        int r = bid - 19456;
        do_gen(w_hh, g_wf32_hh, g_w16_hh, H_, kw2a, kw2b, 1,
               3, r & 31, r >> 5, 7);
    } else if (bid < 24576) {
        int lb = bid - 23552;
        do_mma(g_code_hx, H_, g_w16_hh, g_bq_hh, g_bn_hh, 0, g_pb_hh,
               g_list1, &g_cnt[1], 2, 3, 4, 4096,
               (lb & 31) * 128, (lb >> 5) * 128);
    } else {
        int lb = bid - 24576;
        do_mma(g_code_hx, H_, g_w16_hh, g_bq_hh, g_bn_hh, 0, g_pb_hh,
               g_list1, &g_cnt[1], 3, 4, 4, 4096,
               (lb & 31) * 128, (lb >> 5) * 128);
    }
}

// ---------------- exact fixup (ascending-k fp32 chain) ----------------
__global__ void k_fixup(const unsigned char* __restrict__ codes, int K,
                        const float* __restrict__ wf32,
                        const float* __restrict__ bq, const float* __restrict__ bn,
                        unsigned char* __restrict__ nib,   // one of nib/pb null
                        unsigned char* __restrict__ pb,
                        const uint32_t* __restrict__ list,
                        const int* __restrict__ cnt) {
    __shared__ float terms[8][1024];
    int wid = threadIdx.x >> 5, lid = threadIdx.x & 31;
    int nwarp = gridDim.x * 8;
    int total = min(*cnt, CAPF);
    for (int e = blockIdx.x * 8 + wid; e < total; e += nwarp) {
        uint32_t ent = list[e];
        int b = ent >> 12, n = ent & 0xFFF;
        unsigned char v = 0;
        for (int m = 0; m < 4; m++) {
            int shift = 3 - m;
            const float* wr = wf32 + ((size_t)m * N4H + n) * K;
            for (int k = lid; k < K; k += 32) {
                int bit = (codes[(size_t)b * K + k] >> shift) & 1;
                terms[wid][k] = bit ? wr[k] : 0.0f;
            }
            __syncwarp();
            if (lid == 0) {
                float acc = 0.0f;
                for (int k = 0; k < K; k++)
                    if (terms[wid][k] != 0.0f)
                        acc = __fadd_rn(acc, terms[wid][k]);
                float x = __fadd_rn(__fadd_rn(acc, bq[m * N4H + n]),
                                    bn[m * N4H + n]);
                int bit = x > 0.5f;
                v |= (unsigned char)(bit << shift);
                if (pb) pb[(size_t)m * BN_SZ + (size_t)b * N4H + n] =
                            (unsigned char)bit;
            }
            __syncwarp();
        }
        if (lid == 0 && nib) nib[(size_t)b * N4H + n] = v;
    }
}

// ---------------- fused recombine + LSTM tail ----------------
__device__ __forceinline__ float clipa(float x, float aa) {
    return fminf(fmaxf(x, -aa), aa);
}
__device__ __forceinline__ float quantf(float x, float r) {
    float xs = fminf(fmaxf(__fdiv_rn(x, r), -0.9921875f), 0.9921875f);
    return __fmul_rn(__fmul_rn(rintf(__fmul_rn(xs, 128.0f)), 0.0078125f), r);
}
__device__ __forceinline__ float sigm(float x) {
    return __fadd_rn(0.5f, __fmul_rn(0.5f, tanhf(__fmul_rn(0.5f, x))));
}
__device__ __forceinline__ float partnib(unsigned char c, float a) {
    const float c0 = 8.0f/15.0f, c1 = 4.0f/15.0f, c2 = 2.0f/15.0f, c3 = 1.0f/15.0f;
    float s = __fmul_rn(c0, (float)((c >> 3) & 1u));
    s = __fadd_rn(s, __fmul_rn(c1, (float)((c >> 2) & 1u)));
    s = __fadd_rn(s, __fmul_rn(c2, (float)((c >> 1) & 1u)));
    s = __fadd_rn(s, __fmul_rn(c3, (float)(c & 1u)));
    return __fsub_rn(__fmul_rn(s, __fmul_rn(a, 2.0f)), a);
}
__device__ __forceinline__ float partpb(size_t off, float a) {
    const float c0 = 8.0f/15.0f, c1 = 4.0f/15.0f, c2 = 2.0f/15.0f, c3 = 1.0f/15.0f;
    float s = __fmul_rn(c0, (float)g_pb_hh[off]);
    s = __fadd_rn(s, __fmul_rn(c1, (float)g_pb_hh[BN_SZ + off]));
    s = __fadd_rn(s, __fmul_rn(c2, (float)g_pb_hh[2 * BN_SZ + off]));
    s = __fadd_rn(s, __fmul_rn(c3, (float)g_pb_hh[3 * BN_SZ + off]));
    return __fsub_rn(__fmul_rn(s, __fmul_rn(a, 2.0f)), a);
}

__global__ void k_tail(const float* __restrict__ cx, float* __restrict__ outh,
                       float* __restrict__ outc, const float* p1, const float* p3,
                       const float* p4, const float* p5, const float* p6,
                       const float* p7, const float* p8, const float* p9,
                       const float* p10, const float* p11) {
    int idx = blockIdx.x * blockDim.x + threadIdx.x;
    if (idx >= B_ * H_) return;
    int b = idx >> 10, h = idx & 1023;
    float a1 = p1[0], a11v = p11[0];
    const unsigned char* n1 = g_nib_ih + (size_t)b * N4H;
    size_t o2 = (size_t)b * N4H;
    float gi = __fadd_rn(partnib(n1[h], a1), partpb(o2 + h, a11v));
    float gj = __fadd_rn(partnib(n1[H_ + h], a1), partpb(o2 + H_ + h, a11v));
    float gf = __fadd_rn(partnib(n1[2*H_ + h], a1), partpb(o2 + 2*H_ + h, a11v));
    float go = __fadd_rn(partnib(n1[3*H_ + h], a1), partpb(o2 + 3*H_ + h, a11v));
    float a3 = p3[0], a4 = p4[0], a5 = p5[0], a6 = p6[0], a7 = p7[0];
    float a8 = p8[0], a9 = p9[0], a10 = p10[0];
    float fg  = quantf(clipa(sigm(gf), a3), a3);
    float ig  = quantf(clipa(sigm(gi), a4), a4);
    float act = quantf(clipa(tanhf(gj), a5), a5);
    float og  = quantf(clipa(sigm(go), a6), a6);
    float gc  = quantf(clipa(__fmul_rn(cx[idx], fg), a7), a7);
    float ai  = quantf(clipa(__fmul_rn(ig, act), a8), a8);
    float nc  = quantf(clipa(__fadd_rn(gc, ai), a9), a9);
    float acl = quantf(clipa(tanhf(nc), a10), a10);
    outh[idx] = quantf(clipa(__fmul_rn(acl, og), a11v), a11v);
    outc[idx] = nc;
}

// ---------------- launch ----------------
extern "C" void kernel_launch(void* const* d_in, const int* in_sizes, int n_in,
                              void* d_out, int out_size) {
    const float* input = (const float*)d_in[0];
    const float* hx    = (const float*)d_in[1];
    const float* cx    = (const float*)d_in[2];
    const float* w_ih  = (const float*)d_in[3];
    const float* w_hh  = (const float*)d_in[4];
    const float* b_ih  = (const float*)d_in[5];
    const float* b_hh  = (const float*)d_in[6];
    const float* a1  = (const float*)d_in[7];
    const float* a3  = (const float*)d_in[8];
    const float* a4  = (const float*)d_in[9];
    const float* a5  = (const float*)d_in[10];
    const float* a6  = (const float*)d_in[11];
    const float* a7  = (const float*)d_in[12];
    const float* a8  = (const float*)d_in[13];
    const float* a9  = (const float*)d_in[14];
    const float* a10 = (const float*)d_in[15];
    const float* a11 = (const float*)d_in[16];
    float* outh = (float*)d_out;
    float* outc = (float*)d_out + (size_t)B_ * H_;

    uint32_t k1a, k1b, k2a, k2b;
    tf2x32(0u, 42u, 0u, 0u, &k1a, &k1b);
    tf2x32(0u, 42u, 0u, 1u, &k2a, &k2b);
    uint32_t kw1a, kw1b, kb1a, kb1b, kw2a, kw2b, kb2a, kb2b;
    tf2x32(k1a, k1b, 0u, 0u, &kw1a, &kw1b);
    tf2x32(k1a, k1b, 0u, 1u, &kb1a, &kb1b);
    tf2x32(k2a, k2b, 0u, 0u, &kw2a, &kw2b);
    tf2x32(k2a, k2b, 0u, 1u, &kb2a, &kb2b);

    float *pwf_ih, *pwf_hh, *pbq_ih, *pbn_ih, *pbq_hh, *pbn_hh;
    unsigned char *pcode_in, *pcode_hx, *pnib_ih, *ppb_hh;
    uint32_t *plist0, *plist1;
    int* pcnt;
    cudaGetSymbolAddress((void**)&pwf_ih, g_wf32_ih);
    cudaGetSymbolAddress((void**)&pwf_hh, g_wf32_hh);
    cudaGetSymbolAddress((void**)&pbq_ih, g_bq_ih);
    cudaGetSymbolAddress((void**)&pbn_ih, g_bn_ih);
    cudaGetSymbolAddress((void**)&pbq_hh, g_bq_hh);
    cudaGetSymbolAddress((void**)&pbn_hh, g_bn_hh);
    cudaGetSymbolAddress((void**)&pcode_in, g_code_in);
    cudaGetSymbolAddress((void**)&pcode_hx, g_code_hx);
    cudaGetSymbolAddress((void**)&pnib_ih, g_nib_ih);
    cudaGetSymbolAddress((void**)&ppb_hh, g_pb_hh);
    cudaGetSymbolAddress((void**)&plist0, g_list0);
    cudaGetSymbolAddress((void**)&plist1, g_list1);
    cudaGetSymbolAddress((void**)&pcnt, g_cnt);

    const int nb = M_ * N4H;
    k_init<<<1, 32>>>();
    k_maxred<<<512, 256>>>(w_ih, M_ * I_ * N4H, 0);
    k_maxred<<<512, 256>>>(w_hh, M_ * H_ * N4H, 1);
    k_maxred<<<64, 256>>>(b_ih, nb, 2);
    k_maxred<<<64, 256>>>(b_hh, nb, 3);
    k_genb<<<(nb + 255) / 256, 256>>>(b_ih, pbq_ih, pbn_ih, nb, kb1a, kb1b, 2);
    k_genb<<<(nb + 255) / 256, 256>>>(b_hh, pbq_hh, pbn_hh, nb, kb2a, kb2b, 3);
    k_code<<<(B_ * I_ + 255) / 256, 256>>>(input, pcode_in, B_ * I_, a1, a1);
    k_code<<<(B_ * H_ + 255) / 256, 256>>>(hx, pcode_hx, B_ * H_, a11, a1);

    k_fused<<<25600, 256>>>(w_ih, w_hh, kw1a, kw1b, kw2a, kw2b);

    k_fixup<<<512, 256>>>(pcode_in, I_, pwf_ih, pbq_ih, pbn_ih, pnib_ih, 0,
                          plist0, pcnt);
    k_fixup<<<512, 256>>>(pcode_hx, H_, pwf_hh, pbq_hh, pbn_hh, 0, ppb_hh,
                          plist1, pcnt + 1);

    k_tail<<<(B_ * H_ + 255) / 256, 256>>>(cx, outh, outc, a1, a3, a4, a5, a6,
                                           a7, a8, a9, a10, a11);
}

// round 9
// speedup vs baseline: 1.8816x; 1.1403x over previous
#include <cuda_runtime.h>
#include <cuda_fp16.h>
#include <stdint.h>

#define B_ 4096
#define I_ 256
#define H_ 1024
#define N4H 4096
#define M_ 4
#define EPSM 1e-2f
#define CAPF (1<<20)
#define BN_SZ ((size_t)B_*N4H)

// ---------------- device scratch ----------------
__device__ float    g_wf32_ih[M_*N4H*I_];
__device__ float    g_wf32_hh[M_*N4H*H_];
__device__ uint32_t g_w16_ih[M_*N4H*I_];
__device__ uint32_t g_w16_hh[M_*N4H*H_];
__device__ float g_bq_ih[M_*N4H], g_bn_ih[M_*N4H], g_bq_hh[M_*N4H], g_bn_hh[M_*N4H];
__device__ unsigned char g_code_in[B_*I_], g_code_hx[B_*H_];
__device__ unsigned char g_pb_ih[4*BN_SZ];     // per-plane decision bytes (ih)
__device__ unsigned char g_pb_hh[4*BN_SZ];     // per-plane decision bytes (hh)
__device__ float g_max[4];
__device__ int g_cnt[2];
__device__ int g_dnb[8][32];                   // gen tiles done per (plane,row) x nblock128
__device__ int g_mdone[2];                     // mma CTAs done (ih, hh)
__device__ int g_fdone[2];                     // fixup CTAs done
__device__ uint32_t g_list0[CAPF], g_list1[CAPF];

// ---------------- threefry2x32 (JAX exact) ----------------
__host__ __device__ __forceinline__ uint32_t rotl32(uint32_t x, int r) {
    return (x << r) | (x >> (32 - r));
}
// plain version (host key chain + small kernels)
__host__ __device__ __forceinline__ void tf2x32(uint32_t k0, uint32_t k1,
                                                uint32_t x0, uint32_t x1,
                                                uint32_t* o0, uint32_t* o1) {
    uint32_t ks0 = k0, ks1 = k1, ks2 = k0 ^ k1 ^ 0x1BD11BDAu;
    x0 += ks0; x1 += ks1;
#define TF_RND(r) { x0 += x1; x1 = rotl32(x1, r); x1 ^= x0; }
    TF_RND(13) TF_RND(15) TF_RND(26) TF_RND(6)
    x0 += ks1; x1 += ks2 + 1u;
    TF_RND(17) TF_RND(29) TF_RND(16) TF_RND(24)
    x0 += ks2; x1 += ks0 + 2u;
    TF_RND(13) TF_RND(15) TF_RND(26) TF_RND(6)
    x0 += ks0; x1 += ks1 + 3u;
    TF_RND(17) TF_RND(29) TF_RND(16) TF_RND(24)
    x0 += ks1; x1 += ks2 + 4u;
    TF_RND(13) TF_RND(15) TF_RND(26) TF_RND(6)
    x0 += ks2; x1 += ks0 + 5u;
#undef TF_RND
    *o0 = x0; *o1 = x1;
}
// pipe-balanced device version (identical math): alternate SHF-rotate with
// IMAD.WIDE-rotate (x*2^r gives hi|lo on the fma pipe, single LOP3 for (hi|lo)^x0)
__device__ __forceinline__ uint32_t rotl_mul(uint32_t x, int r) {
    uint64_t p = (uint64_t)x * (uint64_t)(1u << r);
    return (uint32_t)p | (uint32_t)(p >> 32);
}
__device__ __forceinline__ void tf2x32_bal(uint32_t k0, uint32_t k1,
                                           uint32_t x0, uint32_t x1,
                                           uint32_t* o0, uint32_t* o1) {
    uint32_t ks0 = k0, ks1 = k1, ks2 = k0 ^ k1 ^ 0x1BD11BDAu;
    x0 += ks0; x1 += ks1;
#define RA(r) { x0 += x1; x1 = rotl_mul(x1, r) ^ x0; }
#define RB(r) { x0 += x1; x1 = rotl32(x1, r) ^ x0; }
    RA(13) RB(15) RA(26) RB(6)
    x0 += ks1; x1 += ks2 + 1u;
    RA(17) RB(29) RA(16) RB(24)
    x0 += ks2; x1 += ks0 + 2u;
    RA(13) RB(15) RA(26) RB(6)
    x0 += ks0; x1 += ks1 + 3u;
    RA(17) RB(29) RA(16) RB(24)
    x0 += ks1; x1 += ks2 + 4u;
    RA(13) RB(15) RA(26) RB(6)
    x0 += ks2; x1 += ks0 + 5u;
#undef RA
#undef RB
    *o0 = x0; *o1 = x1;
}

__device__ __forceinline__ float erfinv_xla(float x) {
    float w = -log1pf(-__fmul_rn(x, x));
    float p;
    if (w < 5.0f) {
        w = w - 2.5f;
        p = 2.81022636e-08f;
        p = fmaf(p, w, 3.43273939e-07f);
        p = fmaf(p, w, -3.5233877e-06f);
        p = fmaf(p, w, -4.39150654e-06f);
        p = fmaf(p, w, 0.00021858087f);
        p = fmaf(p, w, -0.00125372503f);
        p = fmaf(p, w, -0.00417768164f);
        p = fmaf(p, w, 0.246640727f);
        p = fmaf(p, w, 1.50140941f);
    } else {
        w = sqrtf(w) - 3.0f;
        p = -0.000200214257f;
        p = fmaf(p, w, 0.000100950558f);
        p = fmaf(p, w, 0.00134934322f);
        p = fmaf(p, w, -0.00367342844f);
        p = fmaf(p, w, 0.00573950773f);
        p = fmaf(p, w, -0.0076224613f);
        p = fmaf(p, w, 0.00943887047f);
        p = fmaf(p, w, 1.00167406f);
        p = fmaf(p, w, 2.83297682f);
    }
    return __fmul_rn(p, x);
}
__device__ __forceinline__ float normal_from_bits(uint32_t bits) {
    float f = __uint_as_float((bits >> 9) | 0x3f800000u) - 1.0f;
    const float lo = -0.99999994f;
    float u = fmaxf(lo, __fadd_rn(__fmul_rn(f, 2.0f), lo));
    return __fmul_rn(1.41421356f, erfinv_xla(u));
}
__device__ __forceinline__ float quant8(float x) {
    float xs = fminf(fmaxf(x, -0.9921875f), 0.9921875f);
    return __fmul_rn(rintf(__fmul_rn(xs, 128.0f)), 0.0078125f);
}
__device__ __forceinline__ float weff_val(const float* W, int j, uint32_t k0,
                                          uint32_t k1, float wmax) {
    uint32_t o0, o1;
    tf2x32_bal(k0, k1, 0u, (uint32_t)j, &o0, &o1);
    float nrm = normal_from_bits(o0 ^ o1);
    return __fadd_rn(quant8(W[j]), __fmul_rn(__fmul_rn(nrm, wmax), 0.1f));
}

// ---------------- PTX helpers ----------------
__device__ __forceinline__ uint32_t smem_u32(const void* p) {
    uint32_t a;
    asm("{ .reg .u64 t; cvta.to.shared.u64 t, %1; cvt.u32.u64 %0, t; }" : "=r"(a) : "l"(p));
    return a;
}
__device__ __forceinline__ void cpa16(uint32_t dst, const void* src) {
    asm volatile("cp.async.cg.shared.global [%0], [%1], 16;" :: "r"(dst), "l"(src));
}
#define CPA_COMMIT() asm volatile("cp.async.commit_group;" ::: "memory")
#define LDMX4(r, a) asm volatile( \
    "ldmatrix.sync.aligned.m8n8.x4.shared.b16 {%0,%1,%2,%3}, [%4];" \
    : "=r"((r)[0]), "=r"((r)[1]), "=r"((r)[2]), "=r"((r)[3]) : "r"(a))
#define HMMA(c, a, bb0, bb1) asm volatile( \
    "mma.sync.aligned.m16n8k16.row.col.f32.f16.f16.f32 " \
    "{%0,%1,%2,%3},{%4,%5,%6,%7},{%8,%9},{%0,%1,%2,%3};" \
    : "+f"((c)[0]), "+f"((c)[1]), "+f"((c)[2]), "+f"((c)[3]) \
    : "r"((a)[0]), "r"((a)[1]), "r"((a)[2]), "r"((a)[3]), "r"(bb0), "r"(bb1))

__device__ __forceinline__ void spinv(volatile int* p, int target) {
    if (threadIdx.x == 0) {
        while (*p < target) __nanosleep(100);
        __threadfence();
    }
    __syncthreads();
}

// ---------------- prologue kernels ----------------
__global__ void k_init() {
    int t = threadIdx.x;
    if (t < 4) g_max[t] = 0.0f;
    if (t < 2) { g_cnt[t] = 0; g_mdone[t] = 0; g_fdone[t] = 0; }
    ((int*)g_dnb)[t] = 0;   // 256 ints
}
__global__ void k_maxred(const float* __restrict__ x, int n, int slot) {
    float m = 0.0f;
    for (int i = blockIdx.x * blockDim.x + threadIdx.x; i < n;
         i += gridDim.x * blockDim.x)
        m = fmaxf(m, x[i]);
    for (int o = 16; o; o >>= 1)
        m = fmaxf(m, __shfl_xor_sync(0xffffffffu, m, o));
    if ((threadIdx.x & 31) == 0)
        atomicMax((int*)&g_max[slot], __float_as_int(m));
}
__global__ void k_genb(const float* __restrict__ bsrc, float* __restrict__ bq,
                       float* __restrict__ bn, int n, uint32_t k0, uint32_t k1,
                       int maxslot) {
    int j = blockIdx.x * blockDim.x + threadIdx.x;
    if (j >= n) return;
    uint32_t o0, o1;
    tf2x32_bal(k0, k1, 0u, (uint32_t)j, &o0, &o1);
    float nrm = normal_from_bits(o0 ^ o1);
    bq[j] = quant8(bsrc[j]);
    bn[j] = __fmul_rn(__fmul_rn(nrm, g_max[maxslot]), 0.1f);
}
__global__ void k_code(const float* __restrict__ x, unsigned char* __restrict__ code,
                       int n, const float* __restrict__ aclip,
                       const float* __restrict__ aoff) {
    int i = blockIdx.x * blockDim.x + threadIdx.x;
    if (i >= n) return;
    float ac = aclip[0], off = aoff[0];
    float xc = fminf(fmaxf(x[i], -ac), ac);
    float v01 = __fdiv_rn(__fadd_rn(xc, off), __fmul_rn(ac, 2.0f));
    int v = (int)rintf(__fmul_rn(15.0f, v01));
    code[i] = (unsigned char)(v & 15);
}

// ---------------- role: gen one 32k x 32n tile of plane m ----------------
__device__ void do_gen(char* dsm, const float* __restrict__ W,
                       float* __restrict__ wf32, uint32_t* __restrict__ w16, int K,
                       uint32_t key0, uint32_t key1, int maxslot,
                       int m, int kt, int nt, int dnbrow) {
    float (*tf)[33] = (float(*)[33])dsm;
    uint32_t (*th)[33] = (uint32_t(*)[33])(dsm + 4224);
    const int tid = threadIdx.x;
    const int kk0 = kt * 32, nn0 = nt * 32;
    const int tx = tid & 31, ty = tid >> 5;
    const float wmax = g_max[maxslot];
#pragma unroll
    for (int r = ty; r < 32; r += 8) {
        int j = (m * K + kk0 + r) * N4H + nn0 + tx;
        float w = weff_val(W, j, key0, key1, wmax);
        __half hi = __float2half_rn(w);
        float r1 = __fsub_rn(w, __half2float(hi));
        __half lo = __float2half_rn(r1);
        tf[r][tx] = w;
        th[r][tx] = (uint32_t)__half_as_ushort(hi) |
                    ((uint32_t)__half_as_ushort(lo) << 16);
    }
    __syncthreads();
#pragma unroll
    for (int r = ty; r < 32; r += 8) {
        size_t base = ((size_t)m * N4H + nn0 + r) * K + kk0 + tx;
        wf32[base] = tf[tx][r];
        w16[base] = th[tx][r];
    }
    __threadfence();
    __syncthreads();
    if (tid == 0) atomicAdd(&g_dnb[dnbrow][nt >> 2], 1);
}

// ---------------- role: HMMA 128x128 tile, planes [mstart,mend) --------------
__device__ void do_mma(char* sm, const unsigned char* __restrict__ codes, int K,
                       const uint32_t* __restrict__ w16,
                       const float* __restrict__ bq, const float* __restrict__ bn,
                       unsigned char* __restrict__ pb,
                       uint32_t* __restrict__ list, int* __restrict__ cnt,
                       int mstart, int mend, int dnbrow0, int nbtarget,
                       int n0, int b0, int mdslot) {
    const int tid = threadIdx.x, lane = tid & 31, wid = tid >> 5;
    const int wm = wid & 3, wn = wid >> 2;
    const int NC = (2 * K) / 32;
    const uint32_t sbase = smem_u32(sm);
    uint32_t sA[2] = {sbase, sbase + 20480};
    uint32_t sB[2] = {sbase + 10240, sbase + 30720};

    const int arow = (lane & 7) + ((lane >> 3) & 1) * 8;
    const int akg = (lane >> 4) & 1;
    const int brow = (lane & 7) + ((lane >> 4) & 1) * 8;
    const int bkg = (lane >> 3) & 1;
    const int erow = tid >> 1, eseg = tid & 1;

    for (int m = mstart; m < mend; m++) {
        spinv(&g_dnb[dnbrow0 + m][n0 >> 7], nbtarget);
        const int shift = 3 - m;
        const uint32_t* wmp = w16 + (size_t)m * N4H * K;
        float acc[2][8][4];
#pragma unroll
        for (int i = 0; i < 2; i++)
#pragma unroll
            for (int j = 0; j < 8; j++)
#pragma unroll
                for (int q = 0; q < 4; q++) acc[i][j][q] = 0.0f;

        auto load = [&](int c) {
            int buf = c & 1;
            int kb2 = c * 16;
            {
                const unsigned char* cp =
                    codes + (size_t)(b0 + erow) * K + kb2 + eseg * 8;
                uint64_t cc = *(const uint64_t*)cp;
                uint32_t v[8];
#pragma unroll
                for (int q = 0; q < 8; q++)
                    v[q] = ((((uint32_t)(cc >> (8 * q))) >> shift) & 1u)
                               ? 0x3C003C00u : 0u;
                char* dst = sm + (buf ? 20480 : 0) + erow * 80 + eseg * 32;
                *(uint4*)dst = make_uint4(v[0], v[1], v[2], v[3]);
                *(uint4*)(dst + 16) = make_uint4(v[4], v[5], v[6], v[7]);
            }
#pragma unroll
            for (int q = 0; q < 2; q++) {
                int idx = tid + q * 256;
                int row = idx >> 2, part = idx & 3;
                const uint32_t* g = wmp + (size_t)(n0 + row) * K + kb2 + part * 4;
                cpa16(sB[buf] + row * 80 + part * 16, g);
            }
            CPA_COMMIT();
        };

        load(0);
        for (int c = 0; c < NC; c++) {
            if (c + 1 < NC) {
                load(c + 1);
                asm volatile("cp.async.wait_group 1;" ::: "memory");
            } else {
                asm volatile("cp.async.wait_group 0;" ::: "memory");
            }
            __syncthreads();
            int buf = c & 1;
#pragma unroll
            for (int ks = 0; ks < 2; ks++) {
                uint32_t aF[2][4], bF[4][4];
#pragma unroll
                for (int mi = 0; mi < 2; mi++)
                    LDMX4(aF[mi], sA[buf] + (wm * 32 + mi * 16 + arow) * 80 +
                                      ks * 32 + akg * 16);
#pragma unroll
                for (int nj = 0; nj < 4; nj++)
                    LDMX4(bF[nj], sB[buf] + (wn * 64 + nj * 16 + brow) * 80 +
                                      ks * 32 + bkg * 16);
#pragma unroll
                for (int mi = 0; mi < 2; mi++)
#pragma unroll
                    for (int ni = 0; ni < 8; ni++)
                        HMMA(acc[mi][ni], aF[mi], bF[ni >> 1][(ni & 1) * 2],
                             bF[ni >> 1][(ni & 1) * 2 + 1]);
            }
            __syncthreads();
        }
        // epilogue: threshold + margin flag, plane bytes
#pragma unroll
        for (int mi = 0; mi < 2; mi++)
#pragma unroll
            for (int ni = 0; ni < 8; ni++) {
                int n = n0 + wn * 64 + ni * 8 + (lane & 3) * 2;
                float2 bqv = *(const float2*)&bq[m * N4H + n];
                float2 bnv = *(const float2*)&bn[m * N4H + n];
                int r0 = b0 + wm * 32 + mi * 16 + (lane >> 2);
                float x[4];
                x[0] = __fadd_rn(__fadd_rn(acc[mi][ni][0], bqv.x), bnv.x);
                x[1] = __fadd_rn(__fadd_rn(acc[mi][ni][1], bqv.y), bnv.y);
                x[2] = __fadd_rn(__fadd_rn(acc[mi][ni][2], bqv.x), bnv.x);
                x[3] = __fadd_rn(__fadd_rn(acc[mi][ni][3], bqv.y), bnv.y);
#pragma unroll
                for (int e = 0; e < 4; e++) {
                    int rb = (e < 2) ? r0 : r0 + 8;
                    int nn = n + (e & 1);
                    pb[(size_t)m * BN_SZ + (size_t)rb * N4H + nn] =
                        (unsigned char)(x[e] > 0.5f);
                    if (fabsf(x[e] - 0.5f) < EPSM) {
                        int idx = atomicAdd(cnt, 1);
                        if (idx < CAPF)
                            list[idx] = ((uint32_t)m << 24) |
                                        ((uint32_t)rb << 12) | (uint32_t)nn;
                    }
                }
            }
    }
    __threadfence();
    __syncthreads();
    if (tid == 0) atomicAdd(&g_mdone[mdslot], 1);
}

// ---------------- role: exact plane-wise fixup ----------------
__device__ void do_fixup(char* dsm, const unsigned char* __restrict__ codes, int K,
                         const float* __restrict__ wf32,
                         const float* __restrict__ bq, const float* __restrict__ bn,
                         unsigned char* __restrict__ pb,
                         const uint32_t* __restrict__ list, int* __restrict__ cnt,
                         int mdslot, int mdtarget, int lb, int nCTA, int fslot) {
    spinv(&g_mdone[mdslot], mdtarget);
    float (*terms)[1024] = (float(*)[1024])dsm;
    int wid = threadIdx.x >> 5, lid = threadIdx.x & 31;
    int nwarp = nCTA * 8;
    int total = min(*cnt, CAPF);
    for (int e = lb * 8 + wid; e < total; e += nwarp) {
        uint32_t ent = list[e];
        int m = ent >> 24, b = (ent >> 12) & 0xFFF, n = ent & 0xFFF;
        int shift = 3 - m;
        const float* wr = wf32 + ((size_t)m * N4H + n) * K;
        for (int k = lid; k < K; k += 32) {
            int bit = (codes[(size_t)b * K + k] >> shift) & 1;
            terms[wid][k] = bit ? wr[k] : 0.0f;
        }
        __syncwarp();
        if (lid == 0) {
            float acc = 0.0f;
            for (int k = 0; k < K; k++)
                if (terms[wid][k] != 0.0f)
                    acc = __fadd_rn(acc, terms[wid][k]);
            float x = __fadd_rn(__fadd_rn(acc, bq[m * N4H + n]), bn[m * N4H + n]);
            pb[(size_t)m * BN_SZ + (size_t)b * N4H + n] =
                (unsigned char)(x > 0.5f);
        }
        __syncwarp();
    }
    __syncthreads();
    if (threadIdx.x == 0) {
        __threadfence();
        atomicAdd(&g_fdone[fslot], 1);
    }
}

// ---------------- role: recombine + LSTM tail ----------------
__device__ __forceinline__ float clipa(float x, float aa) {
    return fminf(fmaxf(x, -aa), aa);
}
__device__ __forceinline__ float quantf(float x, float r) {
    float xs = fminf(fmaxf(__fdiv_rn(x, r), -0.9921875f), 0.9921875f);
    return __fmul_rn(__fmul_rn(rintf(__fmul_rn(xs, 128.0f)), 0.0078125f), r);
}
__device__ __forceinline__ float sigm(float x) {
    return __fadd_rn(0.5f, __fmul_rn(0.5f, tanhf(__fmul_rn(0.5f, x))));
}
__device__ __forceinline__ float partpb(const unsigned char* pb, size_t off, float a) {
    const float c0 = 8.0f/15.0f, c1 = 4.0f/15.0f, c2 = 2.0f/15.0f, c3 = 1.0f/15.0f;
    float s = __fmul_rn(c0, (float)pb[off]);
    s = __fadd_rn(s, __fmul_rn(c1, (float)pb[BN_SZ + off]));
    s = __fadd_rn(s, __fmul_rn(c2, (float)pb[2 * BN_SZ + off]));
    s = __fadd_rn(s, __fmul_rn(c3, (float)pb[3 * BN_SZ + off]));
    return __fsub_rn(__fmul_rn(s, __fmul_rn(a, 2.0f)), a);
}

__device__ void do_tail(int lb, const float* __restrict__ cx,
                        float* __restrict__ outh, float* __restrict__ outc,
                        const float* p1, const float* p3, const float* p4,
                        const float* p5, const float* p6, const float* p7,
                        const float* p8, const float* p9, const float* p10,
                        const float* p11) {
    if (threadIdx.x == 0) {
        while (*(volatile int*)&g_fdone[0] < 128) __nanosleep(100);
        while (*(volatile int*)&g_fdone[1] < 256) __nanosleep(100);
        __threadfence();
    }
    __syncthreads();
    int idx = lb * 256 + threadIdx.x;
    int b = idx >> 10, h = idx & 1023;
    float a1 = p1[0], a11v = p11[0];
    size_t o = (size_t)b * N4H;
    float gi = __fadd_rn(partpb(g_pb_ih, o + h, a1), partpb(g_pb_hh, o + h, a11v));
    float gj = __fadd_rn(partpb(g_pb_ih, o + H_ + h, a1),
                         partpb(g_pb_hh, o + H_ + h, a11v));
    float gf = __fadd_rn(partpb(g_pb_ih, o + 2*H_ + h, a1),
                         partpb(g_pb_hh, o + 2*H_ + h, a11v));
    float go = __fadd_rn(partpb(g_pb_ih, o + 3*H_ + h, a1),
                         partpb(g_pb_hh, o + 3*H_ + h, a11v));
    float a3 = p3[0], a4 = p4[0], a5 = p5[0], a6 = p6[0], a7 = p7[0];
    float a8 = p8[0], a9 = p9[0], a10 = p10[0];
    float fg  = quantf(clipa(sigm(gf), a3), a3);
    float ig  = quantf(clipa(sigm(gi), a4), a4);
    float act = quantf(clipa(tanhf(gj), a5), a5);
    float og  = quantf(clipa(sigm(go), a6), a6);
    float gc  = quantf(clipa(__fmul_rn(cx[idx], fg), a7), a7);
    float ai  = quantf(clipa(__fmul_rn(ig, act), a8), a8);
    float nc  = quantf(clipa(__fadd_rn(gc, ai), a9), a9);
    float acl = quantf(clipa(tanhf(nc), a10), a10);
    outh[idx] = quantf(clipa(__fmul_rn(acl, og), a11v), a11v);
    outc[idx] = nc;
}

// ---------------- fused pipeline kernel ----------------
// bid layout (monotone dispatch; all spin deps at strictly lower bids):
// [0,4096)        gen_ih planes 0-3 (1024 each; nt-major within plane)
// [4096,5120)     mma_ih (loops planes 0-3; n-major CTA order)
// [5120,5248)     fixup_ih (128 CTAs; spins mdone[0]==1024)
// per hh plane p (base = 5248 + p*5120):
//   [base,base+4096)       gen_hh plane p (nt-major)
//   [base+4096,base+5120)  mma_hh plane p (n-major)
// [25728,25984)   fixup_hh (256 CTAs; spins mdone[1]==4096)
// [25984,42368)   tail (16384 CTAs; spins fdone)
__global__ __launch_bounds__(256, 2)
void k_fused(const float* __restrict__ w_ih, const float* __restrict__ w_hh,
             uint32_t kw1a, uint32_t kw1b, uint32_t kw2a, uint32_t kw2b,
             const float* __restrict__ cx, float* __restrict__ outh,
             float* __restrict__ outc,
             const float* p1, const float* p3, const float* p4,
             const float* p5, const float* p6, const float* p7,
             const float* p8, const float* p9, const float* p10,
             const float* p11) {
    extern __shared__ char dsm[];
    const int bid = blockIdx.x;
    if (bid < 4096) {
        int m = bid >> 10, r = bid & 1023;       // nt-major: nt = r>>3, kt = r&7
        do_gen(dsm, w_ih, g_wf32_ih, g_w16_ih, I_, kw1a, kw1b, 0,
               m, r & 7, r >> 3, m);
    } else if (bid < 5120) {
        int lb = bid - 4096;                     // n-major
        do_mma(dsm, g_code_in, I_, g_w16_ih, g_bq_ih, g_bn_ih, g_pb_ih,
               g_list0, &g_cnt[0], 0, 4, 0, 32,
               (lb >> 5) * 128, (lb & 31) * 128, 0);
    } else if (bid < 5248) {
        do_fixup(dsm, g_code_in, I_, g_wf32_ih, g_bq_ih, g_bn_ih, g_pb_ih,
                 g_list0, &g_cnt[0], 0, 1024, bid - 5120, 128, 0);
    } else if (bid < 25728) {
        int lb = bid - 5248;
        int p = lb / 5120, r = lb % 5120;
        if (r < 4096) {                          // gen_hh plane p, nt-major
            do_gen(dsm, w_hh, g_wf32_hh, g_w16_hh, H_, kw2a, kw2b, 1,
                   p, r & 31, r >> 5, 4 + p);
        } else {                                 // mma_hh plane p, n-major
            int q = r - 4096;
            do_mma(dsm, g_code_hx, H_, g_w16_hh, g_bq_hh, g_bn_hh, g_pb_hh,
                   g_list1, &g_cnt[1], p, p + 1, 4, 128,
                   (q >> 5) * 128, (q & 31) * 128, 1);
        }
    } else if (bid < 25984) {
        do_fixup(dsm, g_code_hx, H_, g_wf32_hh, g_bq_hh, g_bn_hh, g_pb_hh,
                 g_list1, &g_cnt[1], 1, 4096, bid - 25728, 256, 1);
    } else {
        do_tail(bid - 25984, cx, outh, outc, p1, p3, p4, p5, p6, p7, p8, p9,
                p10, p11);
    }
}

// ---------------- launch ----------------
extern "C" void kernel_launch(void* const* d_in, const int* in_sizes, int n_in,
                              void* d_out, int out_size) {
    const float* input = (const float*)d_in[0];
    const float* hx    = (const float*)d_in[1];
    const float* cx    = (const float*)d_in[2];
    const float* w_ih  = (const float*)d_in[3];
    const float* w_hh  = (const float*)d_in[4];
    const float* b_ih  = (const float*)d_in[5];
    const float* b_hh  = (const float*)d_in[6];
    const float* a1  = (const float*)d_in[7];
    const float* a3  = (const float*)d_in[8];
    const float* a4  = (const float*)d_in[9];
    const float* a5  = (const float*)d_in[10];
    const float* a6  = (const float*)d_in[11];
    const float* a7  = (const float*)d_in[12];
    const float* a8  = (const float*)d_in[13];
    const float* a9  = (const float*)d_in[14];
    const float* a10 = (const float*)d_in[15];
    const float* a11 = (const float*)d_in[16];
    float* outh = (float*)d_out;
    float* outc = (float*)d_out + (size_t)B_ * H_;

    uint32_t k1a, k1b, k2a, k2b;
    tf2x32(0u, 42u, 0u, 0u, &k1a, &k1b);
    tf2x32(0u, 42u, 0u, 1u, &k2a, &k2b);
    uint32_t kw1a, kw1b, kb1a, kb1b, kw2a, kw2b, kb2a, kb2b;
    tf2x32(k1a, k1b, 0u, 0u, &kw1a, &kw1b);
    tf2x32(k1a, k1b, 0u, 1u, &kb1a, &kb1b);
    tf2x32(k2a, k2b, 0u, 0u, &kw2a, &kw2b);
    tf2x32(k2a, k2b, 0u, 1u, &kb2a, &kb2b);

    float *pbq_ih, *pbn_ih, *pbq_hh, *pbn_hh;
    unsigned char *pcode_in, *pcode_hx;
    cudaGetSymbolAddress((void**)&pbq_ih, g_bq_ih);
    cudaGetSymbolAddress((void**)&pbn_ih, g_bn_ih);
    cudaGetSymbolAddress((void**)&pbq_hh, g_bq_hh);
    cudaGetSymbolAddress((void**)&pbn_hh, g_bn_hh);
    cudaGetSymbolAddress((void**)&pcode_in, g_code_in);
    cudaGetSymbolAddress((void**)&pcode_hx, g_code_hx);

    const int nb = M_ * N4H;
    k_init<<<1, 256>>>();
    k_maxred<<<512, 256>>>(w_ih, M_ * I_ * N4H, 0);
    k_maxred<<<512, 256>>>(w_hh, M_ * H_ * N4H, 1);
    k_maxred<<<64, 256>>>(b_ih, nb, 2);
    k_maxred<<<64, 256>>>(b_hh, nb, 3);
    k_genb<<<(nb + 255) / 256, 256>>>(b_ih, pbq_ih, pbn_ih, nb, kb1a, kb1b, 2);
    k_genb<<<(nb + 255) / 256, 256>>>(b_hh, pbq_hh, pbn_hh, nb, kb2a, kb2b, 3);
    k_code<<<(B_ * I_ + 255) / 256, 256>>>(input, pcode_in, B_ * I_, a1, a1);
    k_code<<<(B_ * H_ + 255) / 256, 256>>>(hx, pcode_hx, B_ * H_, a11, a1);

    k_fused<<<42368, 256, 40960>>>(w_ih, w_hh, kw1a, kw1b, kw2a, kw2b,
                                   cx, outh, outc,
                                   a1, a3, a4, a5, a6, a7, a8, a9, a10, a11);
}